// round 1
// baseline (speedup 1.0000x reference)
#include <cuda_runtime.h>

#define N_AGENT 25
#define N_S     32
#define BATCH   2048
#define K1      800        // N_AGENT * N_S
#define EHH     3200       // ehh hidden
#define N2      300        // 25 agents * 12
#define N_EDGE  300

// ---- device scratch (static; no dynamic allocation allowed) ----
__device__ float g_mu[K1];
__device__ float g_rstd[K1];
__device__ float g_neigh[EHH * N_AGENT];      // 320 KB
__device__ float g_w1eff[EHH * N2];           // 3.84 MB
__device__ float g_emb[(size_t)BATCH * EHH];  // 26.2 MB (L2-resident)

__device__ __forceinline__ float leaky(float x) { return x >= 0.f ? x : 0.01f * x; }

// ============================================================
// 1) per-feature batch stats (mean / rsqrt(var+eps) over BATCH)
// ============================================================
__global__ void k_stats(const float* __restrict__ states) {
    int f = blockIdx.x;               // 0..799
    int a = f >> 5, s = f & 31;
    const float* p = states + (size_t)a * BATCH * N_S + s;
    float sum = 0.f, sq = 0.f;
    for (int b = threadIdx.x; b < BATCH; b += 256) {
        float v = p[(size_t)b * N_S];
        sum += v; sq += v * v;
    }
    __shared__ float s1[256], s2[256];
    s1[threadIdx.x] = sum; s2[threadIdx.x] = sq;
    __syncthreads();
    for (int st = 128; st > 0; st >>= 1) {
        if (threadIdx.x < st) {
            s1[threadIdx.x] += s1[threadIdx.x + st];
            s2[threadIdx.x] += s2[threadIdx.x + st];
        }
        __syncthreads();
    }
    if (threadIdx.x == 0) {
        float mu  = s1[0] * (1.f / BATCH);
        float var = s2[0] * (1.f / BATCH) - mu * mu;
        g_mu[f]   = mu;
        g_rstd[f] = rsqrtf(var + 1e-5f);
    }
}

// ============================================================
// 2) neighbor scatter: sequential last-write-wins, two passes
//    (matches XLA scatter update order: .at[adj[:,1]].set then .at[adj[:,3]].set)
// ============================================================
__global__ void k_scatter(const float* __restrict__ anova, const int* __restrict__ adj) {
    int t = threadIdx.x;
    for (int i = t; i < EHH * N_AGENT; i += 256) g_neigh[i] = 0.f;
    __syncthreads();
    if (t < N_AGENT) {
        #pragma unroll
        for (int pass = 0; pass < 2; pass++) {
            int col = (pass == 0) ? 1 : 3;
            for (int e = 0; e < N_EDGE; e++) {
                int row = adj[e * 4 + col];
                int src = adj[e * 4 + 0];
                g_neigh[row * N_AGENT + t] = anova[(size_t)(EHH + src) * N_AGENT + t];
            }
        }
    }
}

// ============================================================
// 3) fold attention into w1: W1eff[h, a*12+k] = (self+neigh)[h,a] * w1[a,h,k]
// ============================================================
__global__ void k_w1eff(const float* __restrict__ anova, const float* __restrict__ w1) {
    int h = blockIdx.x;       // 0..3199
    int n = threadIdx.x;      // 0..299
    int a = n / 12, k = n % 12;
    float att = anova[(size_t)h * N_AGENT + a] + g_neigh[h * N_AGENT + a];
    g_w1eff[(size_t)h * N2 + n] = att * w1[((size_t)a * EHH + h) * 12 + k];
}

// ============================================================
// 4) GEMM1: emb = leaky( normalize(states_reshaped) @ ehh_w )
//    M=2048, K=800, N=3200.  128x128x16 tiles, 8x8 thread tiles.
// ============================================================
__global__ void __launch_bounds__(256) k_gemm1(const float* __restrict__ states,
                                               const float* __restrict__ ehh_w) {
    __shared__ float As[16][132];   // [k][m], padded
    __shared__ float Bs[16][128];   // [k][n]
    int m0 = blockIdx.y * 128;
    int n0 = blockIdx.x * 128;
    int tid = threadIdx.x;
    int tm = tid >> 4, tn = tid & 15;

    float acc[8][8];
    #pragma unroll
    for (int i = 0; i < 8; i++)
        #pragma unroll
        for (int j = 0; j < 8; j++) acc[i][j] = 0.f;

    int lak = tid & 15;          // A: k within tile
    int lam = tid >> 4;          // A: m base, rows lam + 16*r
    int lbn = (tid & 31) * 4;    // B: n (float4)
    int lbk = tid >> 5;          // B: k base (0..7), plus +8

    for (int k0 = 0; k0 < K1; k0 += 16) {
        // A tile: normalize states on the fly. All 16 k's of this tile lie in one agent.
        int a     = k0 >> 5;
        int sbase = k0 & 31;
        float mu = g_mu[k0 + lak];
        float rs = g_rstd[k0 + lak];
        const float* sp = states + (size_t)a * BATCH * N_S + sbase + lak;
        #pragma unroll
        for (int r = 0; r < 8; r++) {
            int m = lam + 16 * r;
            As[lak][m] = (sp[(size_t)(m0 + m) * N_S] - mu) * rs;
        }
        // B tile
        #pragma unroll
        for (int r = 0; r < 2; r++) {
            int k = lbk + 8 * r;
            float4 v = *(const float4*)(ehh_w + (size_t)(k0 + k) * EHH + n0 + lbn);
            *(float4*)&Bs[k][lbn] = v;
        }
        __syncthreads();
        #pragma unroll
        for (int kk = 0; kk < 16; kk++) {
            float af[8], bf[8];
            #pragma unroll
            for (int i = 0; i < 8; i++) af[i] = As[kk][tm * 8 + i];
            #pragma unroll
            for (int j = 0; j < 8; j++) bf[j] = Bs[kk][tn * 8 + j];
            #pragma unroll
            for (int i = 0; i < 8; i++)
                #pragma unroll
                for (int j = 0; j < 8; j++)
                    acc[i][j] += af[i] * bf[j];
        }
        __syncthreads();
    }
    #pragma unroll
    for (int i = 0; i < 8; i++) {
        int m = m0 + tm * 8 + i;
        float* op = g_emb + (size_t)m * EHH + n0 + tn * 8;
        #pragma unroll
        for (int j = 0; j < 8; j++) op[j] = leaky(acc[i][j]);
    }
}

// ============================================================
// 5) GEMM2 + fused tail.
//    h1 = leaky(emb @ W1eff + b1)  (M=2048, K=3200, N=300)
//    then per (b, agent): h2 = leaky(h1@w2+b2); q = h2@w3[:,act] + b3[act]
//    Block: 32 batch rows x 5 agents (60 cols). 240 compute threads (2x4 tiles).
// ============================================================
__global__ void __launch_bounds__(256) k_gemm2(
    const float* __restrict__ b1, const float* __restrict__ w2,
    const float* __restrict__ b2, const float* __restrict__ w3,
    const float* __restrict__ b3, const int* __restrict__ actions,
    float* __restrict__ out)
{
    __shared__ float As[32][33];   // [k][m]
    __shared__ float Bs[32][60];   // [k][n]
    __shared__ float H1[32][60];   // [m][n]
    int m0 = blockIdx.x * 32;
    int g0 = blockIdx.y * 60;      // column offset; agents g0/12 .. g0/12+4
    int tid = threadIdx.x;

    float acc[2][4] = {{0.f,0.f,0.f,0.f},{0.f,0.f,0.f,0.f}};
    bool active = tid < 240;
    int tm = tid / 15, tn = tid % 15;   // only meaningful when active

    int lak = tid & 31;   // A load: k
    int lam = tid >> 5;   // A load: m base (0..7), rows lam + 8*r

    for (int k0 = 0; k0 < EHH; k0 += 32) {
        #pragma unroll
        for (int r = 0; r < 4; r++) {
            int m = lam + 8 * r;
            As[lak][m] = g_emb[(size_t)(m0 + m) * EHH + k0 + lak];
        }
        #pragma unroll 2
        for (int i = tid; i < 32 * 60; i += 256) {
            int k = i / 60, n = i % 60;
            Bs[k][n] = g_w1eff[(size_t)(k0 + k) * N2 + g0 + n];
        }
        __syncthreads();
        if (active) {
            #pragma unroll
            for (int kk = 0; kk < 32; kk++) {
                float a0 = As[kk][tm * 2];
                float a1 = As[kk][tm * 2 + 1];
                float bf[4];
                #pragma unroll
                for (int j = 0; j < 4; j++) bf[j] = Bs[kk][tn * 4 + j];
                #pragma unroll
                for (int j = 0; j < 4; j++) {
                    acc[0][j] += a0 * bf[j];
                    acc[1][j] += a1 * bf[j];
                }
            }
        }
        __syncthreads();
    }
    if (active) {
        #pragma unroll
        for (int i = 0; i < 2; i++)
            #pragma unroll
            for (int j = 0; j < 4; j++) {
                int n  = tn * 4 + j;
                int ng = g0 + n;
                int a  = ng / 12, kk_ = ng % 12;
                H1[tm * 2 + i][n] = leaky(acc[i][j] + b1[a * 12 + kk_]);
            }
    }
    __syncthreads();
    // tail: 32 rows x 5 agents = 160 tasks
    if (tid < 160) {
        int bl = tid / 5, al = tid % 5;
        int a = g0 / 12 + al;
        float h1v[12];
        #pragma unroll
        for (int k = 0; k < 12; k++) h1v[k] = H1[bl][al * 12 + k];
        float h2[12];
        #pragma unroll
        for (int j = 0; j < 12; j++) {
            float s = b2[a * 12 + j];
            #pragma unroll
            for (int k = 0; k < 12; k++) s += h1v[k] * w2[(a * 12 + k) * 12 + j];
            h2[j] = leaky(s);
        }
        int b   = m0 + bl;
        int act = actions[(size_t)a * BATCH + b];
        float q = b3[a * 4 + act];
        #pragma unroll
        for (int j = 0; j < 12; j++) q += h2[j] * w3[(a * 12 + j) * 4 + act];
        out[(size_t)a * BATCH + b] = q;
    }
}

// ============================================================
extern "C" void kernel_launch(void* const* d_in, const int* in_sizes, int n_in,
                              void* d_out, int out_size) {
    const float* states = (const float*)d_in[0];
    const float* ehh_w  = (const float*)d_in[1];
    const float* anova  = (const float*)d_in[2];
    const float* w1     = (const float*)d_in[3];
    const float* b1     = (const float*)d_in[4];
    const float* w2     = (const float*)d_in[5];
    const float* b2     = (const float*)d_in[6];
    const float* w3     = (const float*)d_in[7];
    const float* b3     = (const float*)d_in[8];
    const int* actions  = (const int*)d_in[9];
    const int* adj      = (const int*)d_in[10];
    float* out = (float*)d_out;

    k_stats  <<<K1, 256>>>(states);
    k_scatter<<<1, 256>>>(anova, adj);
    k_w1eff  <<<EHH, N2>>>(anova, w1);
    k_gemm1  <<<dim3(EHH / 128, BATCH / 128), 256>>>(states, ehh_w);
    k_gemm2  <<<dim3(BATCH / 32, N2 / 60), 256>>>(b1, w2, b2, w3, b3, actions, out);
}

// round 3
// speedup vs baseline: 1.4246x; 1.4246x over previous
#include <cuda_runtime.h>

#define N_AGENT 25
#define N_S     32
#define BATCH   2048
#define K1      800        // N_AGENT * N_S
#define EHH     3200
#define N2      300        // 25 * 12
#define N2P     320        // padded
#define N_EDGE  300

typedef unsigned long long u64;

// ---- device scratch ----
__device__ float g_mu[K1];
__device__ float g_rstd[K1];
__device__ float g_neigh[EHH * N_AGENT];
__device__ float g_w1eff[EHH * N2P];            // 4.1 MB (padded to 320 cols)
__device__ float g_emb[(size_t)BATCH * EHH];    // 26.2 MB (L2-resident)
__device__ float g_h1[(size_t)BATCH * N2];      // 2.4 MB

__device__ __forceinline__ float leaky(float x) { return x >= 0.f ? x : 0.01f * x; }
__device__ __forceinline__ u64 pk2(float x, float y) {
    u64 r; asm("mov.b64 %0,{%1,%2};" : "=l"(r) : "f"(x), "f"(y)); return r;
}
__device__ __forceinline__ void fma2(u64& d, u64 a, u64 b) {
    asm("fma.rn.f32x2 %0,%1,%2,%0;" : "+l"(d) : "l"(a), "l"(b));
}
__device__ __forceinline__ float2 up2(u64 v) {
    float2 f; asm("mov.b64 {%0,%1},%2;" : "=f"(f.x), "=f"(f.y) : "l"(v)); return f;
}

// ============================================================
// 1) batch-norm stats
// ============================================================
__global__ void k_stats(const float* __restrict__ states) {
    int f = blockIdx.x;
    int a = f >> 5, s = f & 31;
    const float* p = states + (size_t)a * BATCH * N_S + s;
    float sum = 0.f, sq = 0.f;
    for (int b = threadIdx.x; b < BATCH; b += 256) {
        float v = p[(size_t)b * N_S];
        sum += v; sq += v * v;
    }
    __shared__ float s1[256], s2[256];
    s1[threadIdx.x] = sum; s2[threadIdx.x] = sq;
    __syncthreads();
    for (int st = 128; st > 0; st >>= 1) {
        if (threadIdx.x < st) {
            s1[threadIdx.x] += s1[threadIdx.x + st];
            s2[threadIdx.x] += s2[threadIdx.x + st];
        }
        __syncthreads();
    }
    if (threadIdx.x == 0) {
        float mu  = s1[0] * (1.f / BATCH);
        float var = s2[0] * (1.f / BATCH) - mu * mu;
        g_mu[f]   = mu;
        g_rstd[f] = rsqrtf(var + 1e-5f);
    }
}

// ============================================================
// 2) neighbor scatter (sequential last-write-wins, two passes)
// ============================================================
__global__ void k_scatter(const float* __restrict__ anova, const int* __restrict__ adj) {
    int t = threadIdx.x;
    for (int i = t; i < EHH * N_AGENT; i += 256) g_neigh[i] = 0.f;
    __syncthreads();
    if (t < N_AGENT) {
        #pragma unroll
        for (int pass = 0; pass < 2; pass++) {
            int col = (pass == 0) ? 1 : 3;
            for (int e = 0; e < N_EDGE; e++) {
                int row = adj[e * 4 + col];
                int src = adj[e * 4 + 0];
                g_neigh[row * N_AGENT + t] = anova[(size_t)(EHH + src) * N_AGENT + t];
            }
        }
    }
}

// ============================================================
// 3) fold attention into w1 (padded to 320 cols)
// ============================================================
__global__ void k_w1eff(const float* __restrict__ anova, const float* __restrict__ w1) {
    int h = blockIdx.x;
    int n = threadIdx.x;          // 0..319
    float v = 0.f;
    if (n < N2) {
        int a = n / 12, k = n % 12;
        float att = anova[(size_t)h * N_AGENT + a] + g_neigh[h * N_AGENT + a];
        v = att * w1[((size_t)a * EHH + h) * 12 + k];
    }
    g_w1eff[(size_t)h * N2P + n] = v;
}

// ============================================================
// 4) GEMM1: emb = leaky( normalize(states) @ ehh_w )
//    M=2048 K=800 N=3200; 128x128 tiles, 8x8/thread, f32x2, double-buffered
// ============================================================
__global__ void __launch_bounds__(256, 2) k_gemm1(const float* __restrict__ states,
                                                  const float* __restrict__ ehh_w) {
    __shared__ __align__(16) float As[2][16][130];
    __shared__ __align__(16) float Bs[2][16][128];
    int m0 = blockIdx.y * 128;
    int n0 = blockIdx.x * 128;
    int tid = threadIdx.x;
    int tm = tid >> 4, tn = tid & 15;
    int lak = tid & 15, lam = tid >> 4;
    int lbn = (tid & 31) * 4, lbk = tid >> 5;

    u64 acc[4][8];
    #pragma unroll
    for (int i = 0; i < 4; i++)
        #pragma unroll
        for (int j = 0; j < 8; j++) acc[i][j] = 0ull;

    float sa[8]; float smu, srs; float4 sb0, sb1;
    // prologue: tile 0
    {
        smu = g_mu[lak]; srs = g_rstd[lak];
        const float* sp = states + lak;   // agent 0, sbase 0
        #pragma unroll
        for (int r = 0; r < 8; r++) sa[r] = sp[(size_t)(m0 + lam + 16 * r) * N_S];
        sb0 = *(const float4*)(ehh_w + (size_t)lbk * EHH + n0 + lbn);
        sb1 = *(const float4*)(ehh_w + (size_t)(lbk + 8) * EHH + n0 + lbn);
    }
    #pragma unroll
    for (int r = 0; r < 8; r++) As[0][lak][lam + 16 * r] = (sa[r] - smu) * srs;
    *(float4*)&Bs[0][lbk][lbn] = sb0;
    *(float4*)&Bs[0][lbk + 8][lbn] = sb1;
    __syncthreads();

    for (int k0 = 0; k0 < K1; k0 += 16) {
        int cur = (k0 >> 4) & 1;
        int kn = k0 + 16;
        if (kn < K1) {
            smu = g_mu[kn + lak]; srs = g_rstd[kn + lak];
            const float* sp = states + (size_t)(kn >> 5) * BATCH * N_S + (kn & 31) + lak;
            #pragma unroll
            for (int r = 0; r < 8; r++) sa[r] = sp[(size_t)(m0 + lam + 16 * r) * N_S];
            sb0 = *(const float4*)(ehh_w + (size_t)(kn + lbk) * EHH + n0 + lbn);
            sb1 = *(const float4*)(ehh_w + (size_t)(kn + lbk + 8) * EHH + n0 + lbn);
        }
        #pragma unroll
        for (int kk = 0; kk < 16; kk++) {
            const u64* ap = (const u64*)&As[cur][kk][tm * 8];
            u64 a2[4];
            #pragma unroll
            for (int i = 0; i < 4; i++) a2[i] = ap[i];
            float4 bq0 = *(const float4*)&Bs[cur][kk][tn * 8];
            float4 bq1 = *(const float4*)&Bs[cur][kk][tn * 8 + 4];
            float bf[8] = {bq0.x, bq0.y, bq0.z, bq0.w, bq1.x, bq1.y, bq1.z, bq1.w};
            #pragma unroll
            for (int j = 0; j < 8; j++) {
                u64 bb = pk2(bf[j], bf[j]);
                #pragma unroll
                for (int i = 0; i < 4; i++) fma2(acc[i][j], a2[i], bb);
            }
        }
        if (kn < K1) {
            int nb = cur ^ 1;
            #pragma unroll
            for (int r = 0; r < 8; r++) As[nb][lak][lam + 16 * r] = (sa[r] - smu) * srs;
            *(float4*)&Bs[nb][lbk][lbn] = sb0;
            *(float4*)&Bs[nb][lbk + 8][lbn] = sb1;
        }
        __syncthreads();
    }
    // epilogue
    #pragma unroll
    for (int i = 0; i < 4; i++) {
        float2 u[8];
        #pragma unroll
        for (int j = 0; j < 8; j++) u[j] = up2(acc[i][j]);
        float* op0 = g_emb + (size_t)(m0 + tm * 8 + 2 * i) * EHH + n0 + tn * 8;
        float* op1 = op0 + EHH;
        float4 v0 = {leaky(u[0].x), leaky(u[1].x), leaky(u[2].x), leaky(u[3].x)};
        float4 v1 = {leaky(u[4].x), leaky(u[5].x), leaky(u[6].x), leaky(u[7].x)};
        float4 w0 = {leaky(u[0].y), leaky(u[1].y), leaky(u[2].y), leaky(u[3].y)};
        float4 w1v = {leaky(u[4].y), leaky(u[5].y), leaky(u[6].y), leaky(u[7].y)};
        *(float4*)op0 = v0; *((float4*)op0 + 1) = v1;
        *(float4*)op1 = w0; *((float4*)op1 + 1) = w1v;
    }
}

// ============================================================
// 5) GEMM2: h1 = leaky(emb @ W1eff + b1)
//    M=2048 K=3200 N=320(padded); 128x32 tiles, 8x2/thread, f32x2
// ============================================================
__global__ void __launch_bounds__(256, 2) k_gemm2(const float* __restrict__ b1) {
    __shared__ __align__(16) float As[2][32][130];
    __shared__ __align__(16) float Bs[2][32][32];
    int n0 = blockIdx.x * 32;
    int m0 = blockIdx.y * 128;
    int tid = threadIdx.x;
    int tm = tid >> 4, tn = tid & 15;
    int aq = tid & 7;              // A staging: quad (k/4 within tile)
    int ar0 = tid >> 3;            // A staging: row base (+32*r)
    int bk = tid >> 3, bq = tid & 7;  // B staging

    u64 acc[4][2];
    #pragma unroll
    for (int i = 0; i < 4; i++) { acc[i][0] = 0ull; acc[i][1] = 0ull; }

    float4 sA[4]; float4 sB;
    // prologue tile 0
    #pragma unroll
    for (int r = 0; r < 4; r++)
        sA[r] = *(const float4*)(g_emb + (size_t)(m0 + ar0 + 32 * r) * EHH + aq * 4);
    sB = *(const float4*)(g_w1eff + (size_t)bk * N2P + n0 + bq * 4);
    #pragma unroll
    for (int r = 0; r < 4; r++) {
        As[0][aq * 4 + 0][ar0 + 32 * r] = sA[r].x;
        As[0][aq * 4 + 1][ar0 + 32 * r] = sA[r].y;
        As[0][aq * 4 + 2][ar0 + 32 * r] = sA[r].z;
        As[0][aq * 4 + 3][ar0 + 32 * r] = sA[r].w;
    }
    *(float4*)&Bs[0][bk][bq * 4] = sB;
    __syncthreads();

    for (int k0 = 0; k0 < EHH; k0 += 32) {
        int cur = (k0 >> 5) & 1;
        int kn = k0 + 32;
        if (kn < EHH) {
            #pragma unroll
            for (int r = 0; r < 4; r++)
                sA[r] = *(const float4*)(g_emb + (size_t)(m0 + ar0 + 32 * r) * EHH + kn + aq * 4);
            sB = *(const float4*)(g_w1eff + (size_t)(kn + bk) * N2P + n0 + bq * 4);
        }
        #pragma unroll
        for (int kk = 0; kk < 32; kk++) {
            const u64* ap = (const u64*)&As[cur][kk][tm * 8];
            u64 a2[4];
            #pragma unroll
            for (int i = 0; i < 4; i++) a2[i] = ap[i];
            float2 bv = *(const float2*)&Bs[cur][kk][tn * 2];
            u64 bb0 = pk2(bv.x, bv.x);
            u64 bb1 = pk2(bv.y, bv.y);
            #pragma unroll
            for (int i = 0; i < 4; i++) {
                fma2(acc[i][0], a2[i], bb0);
                fma2(acc[i][1], a2[i], bb1);
            }
        }
        if (kn < EHH) {
            int nb = cur ^ 1;
            #pragma unroll
            for (int r = 0; r < 4; r++) {
                As[nb][aq * 4 + 0][ar0 + 32 * r] = sA[r].x;
                As[nb][aq * 4 + 1][ar0 + 32 * r] = sA[r].y;
                As[nb][aq * 4 + 2][ar0 + 32 * r] = sA[r].z;
                As[nb][aq * 4 + 3][ar0 + 32 * r] = sA[r].w;
            }
            *(float4*)&Bs[nb][bk][bq * 4] = sB;
        }
        __syncthreads();
    }
    // epilogue: + b1, leaky, store to g_h1 (compact 300-col layout)
    int n = n0 + tn * 2;
    if (n < N2) {
        float b1x = b1[n], b1y = b1[n + 1];
        #pragma unroll
        for (int i = 0; i < 4; i++) {
            float2 u0 = up2(acc[i][0]);
            float2 u1 = up2(acc[i][1]);
            float* p = g_h1 + (size_t)(m0 + tm * 8 + 2 * i) * N2 + n;
            float2 lo = {leaky(u0.x + b1x), leaky(u1.x + b1y)};
            float2 hi = {leaky(u0.y + b1x), leaky(u1.y + b1y)};
            *(float2*)p = lo;
            *(float2*)(p + N2) = hi;
        }
    }
}

// ============================================================
// 6) tiny per-agent MLP tail + action gather
//    (FIX vs R2: strided shared loads — block has only 128 threads,
//     previous `if (t < 144)` left w2s[128..143] uninitialized)
// ============================================================
__global__ void k_tail(const float* __restrict__ w2, const float* __restrict__ b2,
                       const float* __restrict__ w3, const float* __restrict__ b3,
                       const int* __restrict__ actions, float* __restrict__ out) {
    __shared__ float w2s[144], w3s[48], b2s[12], b3s[4];
    int a = blockIdx.y;
    int t = threadIdx.x;
    for (int i = t; i < 144; i += 128) w2s[i] = w2[a * 144 + i];
    if (t < 48)  w3s[t] = w3[a * 48 + t];
    if (t < 12)  b2s[t] = b2[a * 12 + t];
    if (t < 4)   b3s[t] = b3[a * 4 + t];
    __syncthreads();
    int b = blockIdx.x * 128 + t;
    const float4* hp = (const float4*)&g_h1[(size_t)b * N2 + a * 12];
    float4 p0 = hp[0], p1 = hp[1], p2 = hp[2];
    float x[12] = {p0.x, p0.y, p0.z, p0.w, p1.x, p1.y, p1.z, p1.w, p2.x, p2.y, p2.z, p2.w};
    int act = actions[(size_t)a * BATCH + b];
    float q = b3s[act];
    #pragma unroll
    for (int j = 0; j < 12; j++) {
        float s = b2s[j];
        #pragma unroll
        for (int k = 0; k < 12; k++) s += x[k] * w2s[k * 12 + j];
        q += leaky(s) * w3s[j * 4 + act];
    }
    out[(size_t)a * BATCH + b] = q;
}

// ============================================================
extern "C" void kernel_launch(void* const* d_in, const int* in_sizes, int n_in,
                              void* d_out, int out_size) {
    const float* states = (const float*)d_in[0];
    const float* ehh_w  = (const float*)d_in[1];
    const float* anova  = (const float*)d_in[2];
    const float* w1     = (const float*)d_in[3];
    const float* b1     = (const float*)d_in[4];
    const float* w2     = (const float*)d_in[5];
    const float* b2     = (const float*)d_in[6];
    const float* w3     = (const float*)d_in[7];
    const float* b3     = (const float*)d_in[8];
    const int* actions  = (const int*)d_in[9];
    const int* adj      = (const int*)d_in[10];
    float* out = (float*)d_out;

    k_stats  <<<K1, 256>>>(states);
    k_scatter<<<1, 256>>>(anova, adj);
    k_w1eff  <<<EHH, N2P>>>(anova, w1);
    k_gemm1  <<<dim3(EHH / 128, BATCH / 128), 256>>>(states, ehh_w);
    k_gemm2  <<<dim3(N2P / 32, BATCH / 128), 256>>>(b1);
    k_tail   <<<dim3(BATCH / 128, N_AGENT), 128>>>(w2, b2, w3, b3, actions, out);
}

// round 4
// speedup vs baseline: 1.9962x; 1.4013x over previous
#include <cuda_runtime.h>

#define N_AGENT 25
#define N_S     32
#define BATCH   2048
#define K1      800        // N_AGENT * N_S
#define EHH     3200
#define N2      300        // 25 * 12
#define N2P     320        // padded
#define N_EDGE  300
#define KSPLIT  5
#define KCH     (EHH / KSPLIT)   // 640

typedef unsigned long long u64;

// ---- device scratch ----
__device__ float g_mu[K1];
__device__ float g_rstd[K1];
__device__ int   g_winner[EHH];
__device__ float g_w1eff[EHH * N2P];                    // 4.1 MB
__device__ float g_emb[(size_t)BATCH * EHH];            // 26.2 MB
__device__ float g_h1p[(size_t)KSPLIT * BATCH * N2P];   // 13.1 MB split-K partials

__device__ __forceinline__ float leaky(float x) { return x >= 0.f ? x : 0.01f * x; }
__device__ __forceinline__ u64 pk2(float x, float y) {
    u64 r; asm("mov.b64 %0,{%1,%2};" : "=l"(r) : "f"(x), "f"(y)); return r;
}
__device__ __forceinline__ void fma2(u64& d, u64 a, u64 b) {
    asm("fma.rn.f32x2 %0,%1,%2,%0;" : "+l"(d) : "l"(a), "l"(b));
}
__device__ __forceinline__ float2 up2(u64 v) {
    float2 f; asm("mov.b64 {%0,%1},%2;" : "=f"(f.x), "=f"(f.y) : "l"(v)); return f;
}

// ============================================================
// 1) batch-norm stats
// ============================================================
__global__ void k_stats(const float* __restrict__ states) {
    int f = blockIdx.x;
    int a = f >> 5, s = f & 31;
    const float* p = states + (size_t)a * BATCH * N_S + s;
    float sum = 0.f, sq = 0.f;
    for (int b = threadIdx.x; b < BATCH; b += 256) {
        float v = p[(size_t)b * N_S];
        sum += v; sq += v * v;
    }
    __shared__ float s1[256], s2[256];
    s1[threadIdx.x] = sum; s2[threadIdx.x] = sq;
    __syncthreads();
    for (int st = 128; st > 0; st >>= 1) {
        if (threadIdx.x < st) {
            s1[threadIdx.x] += s1[threadIdx.x + st];
            s2[threadIdx.x] += s2[threadIdx.x + st];
        }
        __syncthreads();
    }
    if (threadIdx.x == 0) {
        float mu  = s1[0] * (1.f / BATCH);
        float var = s2[0] * (1.f / BATCH) - mu * mu;
        g_mu[f]   = mu;
        g_rstd[f] = rsqrtf(var + 1e-5f);
    }
}

// ============================================================
// 2) winner index per row: exact last-write-wins of the two
//    sequential scatter passes (.at[adj[:,1]].set then .at[adj[:,3]].set)
// ============================================================
__global__ void k_winner(const int* __restrict__ adj) {
    int t = threadIdx.x;
    for (int i = t; i < EHH; i += 256) g_winner[i] = -1;
    __syncthreads();
    if (t == 0) {
        for (int e = 0; e < N_EDGE; e++) g_winner[adj[e * 4 + 1]] = e;
        for (int e = 0; e < N_EDGE; e++) g_winner[adj[e * 4 + 3]] = e;
    }
}

// ============================================================
// 3) fold attention into w1 (padded to 320 cols; cols>=300 zero)
// ============================================================
__global__ void k_w1eff(const float* __restrict__ anova, const float* __restrict__ w1,
                        const int* __restrict__ adj) {
    int h = blockIdx.x;
    int n = threadIdx.x;          // 0..319
    float v = 0.f;
    if (n < N2) {
        int a = n / 12, k = n % 12;
        int w = g_winner[h];
        float neigh = (w >= 0) ? anova[(size_t)(EHH + adj[w * 4]) * N_AGENT + a] : 0.f;
        v = (anova[(size_t)h * N_AGENT + a] + neigh) * w1[((size_t)a * EHH + h) * 12 + k];
    }
    g_w1eff[(size_t)h * N2P + n] = v;
}

// ============================================================
// 4) GEMM1: emb = leaky( normalize(states) @ ehh_w )
//    M=2048 K=800 N=3200; 128x64 tiles, 8x4/thread, occ 3, double-buffered
// ============================================================
__global__ void __launch_bounds__(256, 3) k_gemm1(const float* __restrict__ states,
                                                  const float* __restrict__ ehh_w) {
    __shared__ __align__(16) float As[2][16][132];
    __shared__ __align__(16) float Bs[2][16][64];
    int m0 = blockIdx.y * 128;
    int n0 = blockIdx.x * 64;
    int tid = threadIdx.x;
    int tm = tid >> 4, tn = tid & 15;
    int lak = tid & 15, lam = tid >> 4;   // A stage: k, m-base
    int bk = tid >> 4, bq = tid & 15;     // B stage: k row, quad

    u64 acc[4][4];
    #pragma unroll
    for (int i = 0; i < 4; i++)
        #pragma unroll
        for (int j = 0; j < 4; j++) acc[i][j] = 0ull;

    float sa[8]; float smu, srs; float4 sb;
    // prologue: tile 0 (agent 0, sbase 0)
    smu = g_mu[lak]; srs = g_rstd[lak];
    {
        const float* sp = states + lak;
        #pragma unroll
        for (int r = 0; r < 8; r++) sa[r] = sp[(size_t)(m0 + lam + 16 * r) * N_S];
        sb = *(const float4*)(ehh_w + (size_t)bk * EHH + n0 + bq * 4);
    }
    #pragma unroll
    for (int r = 0; r < 8; r++) As[0][lak][lam + 16 * r] = (sa[r] - smu) * srs;
    *(float4*)&Bs[0][bk][bq * 4] = sb;
    __syncthreads();

    for (int k0 = 0; k0 < K1; k0 += 16) {
        int cur = (k0 >> 4) & 1;
        int kn = k0 + 16;
        if (kn < K1) {
            smu = g_mu[kn + lak]; srs = g_rstd[kn + lak];
            const float* sp = states + (size_t)(kn >> 5) * BATCH * N_S + (kn & 31) + lak;
            #pragma unroll
            for (int r = 0; r < 8; r++) sa[r] = sp[(size_t)(m0 + lam + 16 * r) * N_S];
            sb = *(const float4*)(ehh_w + (size_t)(kn + bk) * EHH + n0 + bq * 4);
        }
        #pragma unroll
        for (int kk = 0; kk < 16; kk++) {
            ulonglong2 A01 = *(const ulonglong2*)&As[cur][kk][tm * 8];
            ulonglong2 A23 = *(const ulonglong2*)&As[cur][kk][tm * 8 + 4];
            float4 bv = *(const float4*)&Bs[cur][kk][tn * 4];
            u64 b0 = pk2(bv.x, bv.x), b1 = pk2(bv.y, bv.y);
            u64 b2 = pk2(bv.z, bv.z), b3 = pk2(bv.w, bv.w);
            fma2(acc[0][0], A01.x, b0); fma2(acc[0][1], A01.x, b1);
            fma2(acc[0][2], A01.x, b2); fma2(acc[0][3], A01.x, b3);
            fma2(acc[1][0], A01.y, b0); fma2(acc[1][1], A01.y, b1);
            fma2(acc[1][2], A01.y, b2); fma2(acc[1][3], A01.y, b3);
            fma2(acc[2][0], A23.x, b0); fma2(acc[2][1], A23.x, b1);
            fma2(acc[2][2], A23.x, b2); fma2(acc[2][3], A23.x, b3);
            fma2(acc[3][0], A23.y, b0); fma2(acc[3][1], A23.y, b1);
            fma2(acc[3][2], A23.y, b2); fma2(acc[3][3], A23.y, b3);
        }
        if (kn < K1) {
            int nb = cur ^ 1;
            #pragma unroll
            for (int r = 0; r < 8; r++) As[nb][lak][lam + 16 * r] = (sa[r] - smu) * srs;
            *(float4*)&Bs[nb][bk][bq * 4] = sb;
        }
        __syncthreads();
    }
    // epilogue: rows m0 + tm*8 + 2i (+1), cols n0 + tn*4 .. +3
    #pragma unroll
    for (int i = 0; i < 4; i++) {
        float2 u0 = up2(acc[i][0]), u1 = up2(acc[i][1]);
        float2 u2 = up2(acc[i][2]), u3 = up2(acc[i][3]);
        float* lo = g_emb + (size_t)(m0 + tm * 8 + 2 * i) * EHH + n0 + tn * 4;
        float* hi = lo + EHH;
        float4 vlo = {leaky(u0.x), leaky(u1.x), leaky(u2.x), leaky(u3.x)};
        float4 vhi = {leaky(u0.y), leaky(u1.y), leaky(u2.y), leaky(u3.y)};
        *(float4*)lo = vlo;
        *(float4*)hi = vhi;
    }
}

// ============================================================
// 5) GEMM2 split-K: partials of emb @ W1eff
//    M=2048 K=3200(/5) N=320; 128x64 tiles, 8x4/thread, occ 3
// ============================================================
__global__ void __launch_bounds__(256, 3) k_gemm2() {
    __shared__ __align__(16) float As[2][16][132];
    __shared__ __align__(16) float Bs[2][16][64];
    int n0 = blockIdx.x * 64;
    int m0 = blockIdx.y * 128;
    int ks = blockIdx.z;
    int kbase = ks * KCH;
    int tid = threadIdx.x;
    int tm = tid >> 4, tn = tid & 15;
    int lak = tid & 15, lam = tid >> 4;
    int bk = tid >> 4, bq = tid & 15;

    u64 acc[4][4];
    #pragma unroll
    for (int i = 0; i < 4; i++)
        #pragma unroll
        for (int j = 0; j < 4; j++) acc[i][j] = 0ull;

    float sa[8]; float4 sb;
    // prologue tile 0
    #pragma unroll
    for (int r = 0; r < 8; r++)
        sa[r] = g_emb[(size_t)(m0 + lam + 16 * r) * EHH + kbase + lak];
    sb = *(const float4*)(g_w1eff + (size_t)(kbase + bk) * N2P + n0 + bq * 4);
    #pragma unroll
    for (int r = 0; r < 8; r++) As[0][lak][lam + 16 * r] = sa[r];
    *(float4*)&Bs[0][bk][bq * 4] = sb;
    __syncthreads();

    for (int k0 = 0; k0 < KCH; k0 += 16) {
        int cur = (k0 >> 4) & 1;
        int kn = k0 + 16;
        if (kn < KCH) {
            #pragma unroll
            for (int r = 0; r < 8; r++)
                sa[r] = g_emb[(size_t)(m0 + lam + 16 * r) * EHH + kbase + kn + lak];
            sb = *(const float4*)(g_w1eff + (size_t)(kbase + kn + bk) * N2P + n0 + bq * 4);
        }
        #pragma unroll
        for (int kk = 0; kk < 16; kk++) {
            ulonglong2 A01 = *(const ulonglong2*)&As[cur][kk][tm * 8];
            ulonglong2 A23 = *(const ulonglong2*)&As[cur][kk][tm * 8 + 4];
            float4 bv = *(const float4*)&Bs[cur][kk][tn * 4];
            u64 b0 = pk2(bv.x, bv.x), b1 = pk2(bv.y, bv.y);
            u64 b2 = pk2(bv.z, bv.z), b3 = pk2(bv.w, bv.w);
            fma2(acc[0][0], A01.x, b0); fma2(acc[0][1], A01.x, b1);
            fma2(acc[0][2], A01.x, b2); fma2(acc[0][3], A01.x, b3);
            fma2(acc[1][0], A01.y, b0); fma2(acc[1][1], A01.y, b1);
            fma2(acc[1][2], A01.y, b2); fma2(acc[1][3], A01.y, b3);
            fma2(acc[2][0], A23.x, b0); fma2(acc[2][1], A23.x, b1);
            fma2(acc[2][2], A23.x, b2); fma2(acc[2][3], A23.x, b3);
            fma2(acc[3][0], A23.y, b0); fma2(acc[3][1], A23.y, b1);
            fma2(acc[3][2], A23.y, b2); fma2(acc[3][3], A23.y, b3);
        }
        if (kn < KCH) {
            int nb = cur ^ 1;
            #pragma unroll
            for (int r = 0; r < 8; r++) As[nb][lak][lam + 16 * r] = sa[r];
            *(float4*)&Bs[nb][bk][bq * 4] = sb;
        }
        __syncthreads();
    }
    // epilogue: raw partials (no bias/activation)
    #pragma unroll
    for (int i = 0; i < 4; i++) {
        float2 u0 = up2(acc[i][0]), u1 = up2(acc[i][1]);
        float2 u2 = up2(acc[i][2]), u3 = up2(acc[i][3]);
        float* lo = g_h1p + ((size_t)ks * BATCH + m0 + tm * 8 + 2 * i) * N2P + n0 + tn * 4;
        float* hi = lo + N2P;
        float4 vlo = {u0.x, u1.x, u2.x, u3.x};
        float4 vhi = {u0.y, u1.y, u2.y, u3.y};
        *(float4*)lo = vlo;
        *(float4*)hi = vhi;
    }
}

// ============================================================
// 6) reduce split-K partials + bias + leaky + tiny MLP + gather
// ============================================================
__global__ void k_tailred(const float* __restrict__ b1, const float* __restrict__ w2,
                          const float* __restrict__ b2, const float* __restrict__ w3,
                          const float* __restrict__ b3, const int* __restrict__ actions,
                          float* __restrict__ out) {
    __shared__ float w2s[144], w3s[48], b2s[12], b3s[4], b1s[12];
    int a = blockIdx.y;
    int t = threadIdx.x;
    for (int i = t; i < 144; i += 128) w2s[i] = w2[a * 144 + i];
    if (t < 48)  w3s[t] = w3[a * 48 + t];
    if (t < 12)  { b2s[t] = b2[a * 12 + t]; b1s[t] = b1[a * 12 + t]; }
    if (t < 4)   b3s[t] = b3[a * 4 + t];
    __syncthreads();
    int b = blockIdx.x * 128 + t;
    float4 s0 = {0.f,0.f,0.f,0.f}, s1 = s0, s2 = s0;
    #pragma unroll
    for (int ks = 0; ks < KSPLIT; ks++) {
        const float4* p = (const float4*)&g_h1p[((size_t)ks * BATCH + b) * N2P + a * 12];
        float4 p0 = p[0], p1 = p[1], p2 = p[2];
        s0.x += p0.x; s0.y += p0.y; s0.z += p0.z; s0.w += p0.w;
        s1.x += p1.x; s1.y += p1.y; s1.z += p1.z; s1.w += p1.w;
        s2.x += p2.x; s2.y += p2.y; s2.z += p2.z; s2.w += p2.w;
    }
    float x[12] = {s0.x, s0.y, s0.z, s0.w, s1.x, s1.y, s1.z, s1.w, s2.x, s2.y, s2.z, s2.w};
    #pragma unroll
    for (int k = 0; k < 12; k++) x[k] = leaky(x[k] + b1s[k]);
    int act = actions[(size_t)a * BATCH + b];
    float q = b3s[act];
    #pragma unroll
    for (int j = 0; j < 12; j++) {
        float s = b2s[j];
        #pragma unroll
        for (int k = 0; k < 12; k++) s += x[k] * w2s[k * 12 + j];
        q += leaky(s) * w3s[j * 4 + act];
    }
    out[(size_t)a * BATCH + b] = q;
}

// ============================================================
extern "C" void kernel_launch(void* const* d_in, const int* in_sizes, int n_in,
                              void* d_out, int out_size) {
    const float* states = (const float*)d_in[0];
    const float* ehh_w  = (const float*)d_in[1];
    const float* anova  = (const float*)d_in[2];
    const float* w1     = (const float*)d_in[3];
    const float* b1     = (const float*)d_in[4];
    const float* w2     = (const float*)d_in[5];
    const float* b2     = (const float*)d_in[6];
    const float* w3     = (const float*)d_in[7];
    const float* b3     = (const float*)d_in[8];
    const int* actions  = (const int*)d_in[9];
    const int* adj      = (const int*)d_in[10];
    float* out = (float*)d_out;

    k_stats  <<<K1, 256>>>(states);
    k_winner <<<1, 256>>>(adj);
    k_w1eff  <<<EHH, N2P>>>(anova, w1, adj);
    k_gemm1  <<<dim3(EHH / 64, BATCH / 128), 256>>>(states, ehh_w);
    k_gemm2  <<<dim3(N2P / 64, BATCH / 128, KSPLIT), 256>>>();
    k_tailred<<<dim3(BATCH / 128, N_AGENT), 128>>>(b1, w2, b2, w3, b3, actions, out);
}

// round 6
// speedup vs baseline: 3.0010x; 1.5033x over previous
#include <cuda_runtime.h>
#include <cuda_bf16.h>
#include <cstdint>

#define N_AGENT 25
#define N_S     32
#define BATCH   2048
#define K1      800
#define KP1     832            // 13*64
#define EHH     3200           // 50*64
#define N2      300
#define N2P     320
#define N_EDGE  300
#define KSPLIT2 2
#define KCH2    (EHH / KSPLIT2)   // 1600 = 25*64

// smem tile layout (bytes), per buffer: A 128 rows x 144B (hi+lo), B 64 rows x 144B (hi+lo)
#define ROWB    144
#define OFF_AHI 0
#define OFF_ALO 18432
#define OFF_BHI 36864
#define OFF_BLO 46080
#define BUFSZ   55296
#define SMEM_TOT (2 * BUFSZ)

// ---- device scratch ----
__device__ float g_mu[K1];
__device__ float g_rstd[K1];
__device__ int   g_winner[EHH];
__device__ __nv_bfloat16 g_Ahi[(size_t)BATCH * KP1];
__device__ __nv_bfloat16 g_Alo[(size_t)BATCH * KP1];
__device__ __nv_bfloat16 g_Bthi[(size_t)EHH * KP1];
__device__ __nv_bfloat16 g_Btlo[(size_t)EHH * KP1];
__device__ __nv_bfloat16 g_Ehi[(size_t)BATCH * EHH];
__device__ __nv_bfloat16 g_Elo[(size_t)BATCH * EHH];
__device__ __nv_bfloat16 g_W1thi[(size_t)N2P * EHH];
__device__ __nv_bfloat16 g_W1tlo[(size_t)N2P * EHH];
__device__ float g_h1p[(size_t)KSPLIT2 * BATCH * N2P];

__device__ __forceinline__ float leaky(float x) { return x >= 0.f ? x : 0.01f * x; }
__device__ __forceinline__ void bf16split(float x, __nv_bfloat16& h, __nv_bfloat16& l) {
    h = __float2bfloat16(x);
    l = __float2bfloat16(x - __bfloat162float(h));
}
__device__ __forceinline__ uint32_t smem_u32(const void* p) {
    uint32_t a;
    asm("{ .reg .u64 t; cvta.to.shared.u64 t, %1; cvt.u32.u64 %0, t; }" : "=r"(a) : "l"(p));
    return a;
}
__device__ __forceinline__ uint32_t packbf2(float x, float y) {
    __nv_bfloat162 t = __floats2bfloat162_rn(x, y);
    return *(uint32_t*)&t;
}

#define CP16(dst, src) asm volatile("cp.async.cg.shared.global [%0], [%1], 16;" :: "r"(dst), "l"(src))
#define CP_COMMIT()    asm volatile("cp.async.commit_group;")
#define CP_WAIT0()     asm volatile("cp.async.wait_group 0;")
#define CP_WAIT1()     asm volatile("cp.async.wait_group 1;")
#define LDM4(r, addr)  asm volatile("ldmatrix.sync.aligned.m8n8.x4.shared.b16 {%0,%1,%2,%3}, [%4];" \
    : "=r"((r)[0]), "=r"((r)[1]), "=r"((r)[2]), "=r"((r)[3]) : "r"(addr))

__device__ __forceinline__ void mmabf(float* c, const uint32_t* a, uint32_t b0, uint32_t b1) {
    asm volatile(
        "mma.sync.aligned.m16n8k16.row.col.f32.bf16.bf16.f32 "
        "{%0,%1,%2,%3},{%4,%5,%6,%7},{%8,%9},{%0,%1,%2,%3};"
        : "+f"(c[0]), "+f"(c[1]), "+f"(c[2]), "+f"(c[3])
        : "r"(a[0]), "r"(a[1]), "r"(a[2]), "r"(a[3]), "r"(b0), "r"(b1));
}

// ============================================================
// 1) batch-norm stats
// ============================================================
__global__ void k_stats(const float* __restrict__ states) {
    int f = blockIdx.x;
    int a = f >> 5, s = f & 31;
    const float* p = states + (size_t)a * BATCH * N_S + s;
    float sum = 0.f, sq = 0.f;
    for (int b = threadIdx.x; b < BATCH; b += 256) {
        float v = p[(size_t)b * N_S];
        sum += v; sq += v * v;
    }
    __shared__ float s1[256], s2[256];
    s1[threadIdx.x] = sum; s2[threadIdx.x] = sq;
    __syncthreads();
    for (int st = 128; st > 0; st >>= 1) {
        if (threadIdx.x < st) {
            s1[threadIdx.x] += s1[threadIdx.x + st];
            s2[threadIdx.x] += s2[threadIdx.x + st];
        }
        __syncthreads();
    }
    if (threadIdx.x == 0) {
        float mu  = s1[0] * (1.f / BATCH);
        float var = s2[0] * (1.f / BATCH) - mu * mu;
        g_mu[f]   = mu;
        g_rstd[f] = rsqrtf(var + 1e-5f);
    }
}

// ============================================================
// 2) winner index (last-write-wins of both scatter passes)
// ============================================================
__global__ void k_winner(const int* __restrict__ adj) {
    int t = threadIdx.x;
    for (int i = t; i < EHH; i += 256) g_winner[i] = -1;
    __syncthreads();
    if (t == 0) {
        for (int e = 0; e < N_EDGE; e++) g_winner[adj[e * 4 + 1]] = e;
        for (int e = 0; e < N_EDGE; e++) g_winner[adj[e * 4 + 3]] = e;
    }
}

// ============================================================
// 3) W1eff^T bf16 hi/lo: [320 n][3200 k]; rows >=300 zero
// ============================================================
__global__ void k_w1t(const float* __restrict__ anova, const float* __restrict__ w1,
                      const int* __restrict__ adj) {
    int n = blockIdx.x;
    int a = n / 12, kk = n % 12;
    for (int k = threadIdx.x; k < EHH; k += 256) {
        float v = 0.f;
        if (n < N2) {
            int w = g_winner[k];
            float neigh = (w >= 0) ? anova[(size_t)(EHH + adj[w * 4]) * N_AGENT + a] : 0.f;
            v = (anova[(size_t)k * N_AGENT + a] + neigh) * w1[((size_t)a * EHH + k) * 12 + kk];
        }
        __nv_bfloat16 h, l; bf16split(v, h, l);
        g_W1thi[(size_t)n * EHH + k] = h;
        g_W1tlo[(size_t)n * EHH + k] = l;
    }
}

// ============================================================
// 4) A prep: normalized states -> bf16 hi/lo [2048][832]
// ============================================================
__global__ void k_aprep(const float* __restrict__ states) {
    int b = blockIdx.x;
    for (int k = threadIdx.x; k < KP1; k += 256) {
        float x = 0.f;
        if (k < K1) {
            int a = k >> 5, s = k & 31;
            x = (states[((size_t)a * BATCH + b) * N_S + s] - g_mu[k]) * g_rstd[k];
        }
        __nv_bfloat16 h, l; bf16split(x, h, l);
        g_Ahi[(size_t)b * KP1 + k] = h;
        g_Alo[(size_t)b * KP1 + k] = l;
    }
}

// ============================================================
// 5) B prep: transpose ehh_w [800][3200] -> Bt hi/lo [3200][832]
// ============================================================
__global__ void k_btrans(const float* __restrict__ ehh_w) {
    __shared__ float tl[32][33];
    int n0 = blockIdx.x * 32;
    int k0 = blockIdx.y * 32;
    int tx = threadIdx.x, ty = threadIdx.y;   // 32 x 8
    #pragma unroll
    for (int i = 0; i < 4; i++) {
        int kr = ty + 8 * i;
        int kg = k0 + kr;
        tl[kr][tx] = (kg < K1) ? ehh_w[(size_t)kg * EHH + n0 + tx] : 0.f;
    }
    __syncthreads();
    #pragma unroll
    for (int i = 0; i < 4; i++) {
        int nr = ty + 8 * i;
        float v = tl[tx][nr];
        __nv_bfloat16 h, l; bf16split(v, h, l);
        g_Bthi[(size_t)(n0 + nr) * KP1 + k0 + tx] = h;
        g_Btlo[(size_t)(n0 + nr) * KP1 + k0 + tx] = l;
    }
}

// ============================================================
// shared compute core: one K=64 chunk of bf16x3 HMMA
// ============================================================
__device__ __forceinline__ void mma_chunk(uint32_t sbase, const uint32_t* aOff,
                                          const uint32_t* bOff, float acc[2][4][4]) {
    #pragma unroll
    for (int ks = 0; ks < 4; ks++) {
        uint32_t ah[2][4], al[2][4], bh[2][4], bl[2][4];
        #pragma unroll
        for (int i = 0; i < 2; i++) {
            LDM4(ah[i], sbase + OFF_AHI + aOff[i] + ks * 32);
            LDM4(al[i], sbase + OFF_ALO + aOff[i] + ks * 32);
        }
        #pragma unroll
        for (int j = 0; j < 2; j++) {
            LDM4(bh[j], sbase + OFF_BHI + bOff[j] + ks * 32);
            LDM4(bl[j], sbase + OFF_BLO + bOff[j] + ks * 32);
        }
        #pragma unroll
        for (int i = 0; i < 2; i++)
            #pragma unroll
            for (int jj = 0; jj < 4; jj++) {
                float* c = acc[i][jj];
                uint32_t bh0 = bh[jj >> 1][(jj & 1) * 2], bh1 = bh[jj >> 1][(jj & 1) * 2 + 1];
                uint32_t bl0 = bl[jj >> 1][(jj & 1) * 2], bl1 = bl[jj >> 1][(jj & 1) * 2 + 1];
                mmabf(c, ah[i], bh0, bh1);
                mmabf(c, al[i], bh0, bh1);
                mmabf(c, ah[i], bl0, bl1);
            }
    }
}

// stage one chunk into smem buffer via cp.async (A: 128 rows, B: 64 rows, 64 bf16 each)
__device__ __forceinline__ void stage_chunk(uint32_t sbase, int tid,
                                            const __nv_bfloat16* Ahi, const __nv_bfloat16* Alo,
                                            size_t aStride, int aRow0, size_t aCol,
                                            const __nv_bfloat16* Bhi, const __nv_bfloat16* Blo,
                                            size_t bStride, int bRow0, size_t bCol) {
    #pragma unroll
    for (int j = 0; j < 4; j++) {
        int lin = tid + 256 * j;
        int row = lin >> 3, u = lin & 7;
        uint32_t d = sbase + row * ROWB + u * 16;
        const __nv_bfloat16* sh = Ahi + (size_t)(aRow0 + row) * aStride + aCol + u * 8;
        const __nv_bfloat16* sl = Alo + (size_t)(aRow0 + row) * aStride + aCol + u * 8;
        CP16(d + OFF_AHI, sh);
        CP16(d + OFF_ALO, sl);
    }
    #pragma unroll
    for (int j = 0; j < 2; j++) {
        int lin = tid + 256 * j;
        int row = lin >> 3, u = lin & 7;
        uint32_t d = sbase + row * ROWB + u * 16;
        const __nv_bfloat16* sh = Bhi + (size_t)(bRow0 + row) * bStride + bCol + u * 8;
        const __nv_bfloat16* sl = Blo + (size_t)(bRow0 + row) * bStride + bCol + u * 8;
        CP16(d + OFF_BHI, sh);
        CP16(d + OFF_BLO, sl);
    }
}

// ============================================================
// 6) GEMM1 HMMA: emb = leaky(Anorm @ ehh_w), bf16x3
//    block tile 128(m) x 64(n), 13 K-chunks of 64
// ============================================================
__global__ void __launch_bounds__(256) k_mm1() {
    extern __shared__ __align__(16) char smem[];
    uint32_t sb = smem_u32(smem);
    int tid = threadIdx.x;
    int wid = tid >> 5, lid = tid & 31;
    int wm = wid >> 1, wn = wid & 1;
    int trow = lid & 7, th = lid >> 3;
    int m0 = blockIdx.y * 128, n0 = blockIdx.x * 64;

    uint32_t aOff[2], bOff[2];
    #pragma unroll
    for (int i = 0; i < 2; i++)
        aOff[i] = (uint32_t)((wm * 32 + i * 16 + trow + ((th & 1) << 3)) * ROWB + ((th >> 1) << 4));
    #pragma unroll
    for (int j = 0; j < 2; j++)
        bOff[j] = (uint32_t)((wn * 32 + j * 16 + trow + ((th >> 1) << 3)) * ROWB + ((th & 1) << 4));

    float acc[2][4][4];
    #pragma unroll
    for (int i = 0; i < 2; i++)
        #pragma unroll
        for (int j = 0; j < 4; j++)
            #pragma unroll
            for (int r = 0; r < 4; r++) acc[i][j][r] = 0.f;

    stage_chunk(sb, tid, g_Ahi, g_Alo, KP1, m0, 0, g_Bthi, g_Btlo, KP1, n0, 0);
    CP_COMMIT();
    for (int c = 0; c < 13; c++) {
        if (c + 1 < 13) {
            stage_chunk(sb + ((c + 1) & 1) * BUFSZ, tid,
                        g_Ahi, g_Alo, KP1, m0, (size_t)(c + 1) * 64,
                        g_Bthi, g_Btlo, KP1, n0, (size_t)(c + 1) * 64);
            CP_COMMIT();
            CP_WAIT1();
        } else {
            CP_WAIT0();
        }
        __syncthreads();
        mma_chunk(sb + (c & 1) * BUFSZ, aOff, bOff, acc);
        __syncthreads();
    }

    // epilogue: leaky + bf16 hi/lo split, direct stores
    int gid = lid >> 2, tid4 = lid & 3;
    #pragma unroll
    for (int i = 0; i < 2; i++) {
        #pragma unroll
        for (int jj = 0; jj < 4; jj++) {
            int col = n0 + wn * 32 + jj * 8 + tid4 * 2;
            int r0  = m0 + wm * 32 + i * 16 + gid;
            float v0 = leaky(acc[i][jj][0]), v1 = leaky(acc[i][jj][1]);
            float v2 = leaky(acc[i][jj][2]), v3 = leaky(acc[i][jj][3]);
            __nv_bfloat16 h0, l0, h1, l1, h2, l2, h3, l3;
            bf16split(v0, h0, l0); bf16split(v1, h1, l1);
            bf16split(v2, h2, l2); bf16split(v3, h3, l3);
            *(uint32_t*)(g_Ehi + (size_t)r0 * EHH + col)       = packbf2(__bfloat162float(h0), __bfloat162float(h1));
            *(uint32_t*)(g_Elo + (size_t)r0 * EHH + col)       = packbf2(__bfloat162float(l0), __bfloat162float(l1));
            *(uint32_t*)(g_Ehi + (size_t)(r0 + 8) * EHH + col) = packbf2(__bfloat162float(h2), __bfloat162float(h3));
            *(uint32_t*)(g_Elo + (size_t)(r0 + 8) * EHH + col) = packbf2(__bfloat162float(l2), __bfloat162float(l3));
        }
    }
}

// ============================================================
// 7) GEMM2 HMMA: h1 partials = emb @ W1eff (bf16x3, split-K=2)
//    block tile 128 x 64, 25 K-chunks of 64 per split
// ============================================================
__global__ void __launch_bounds__(256) k_mm2() {
    extern __shared__ __align__(16) char smem[];
    uint32_t sb = smem_u32(smem);
    int tid = threadIdx.x;
    int wid = tid >> 5, lid = tid & 31;
    int wm = wid >> 1, wn = wid & 1;
    int trow = lid & 7, th = lid >> 3;
    int n0 = blockIdx.x * 64, m0 = blockIdx.y * 128;
    int ks2 = blockIdx.z;
    size_t kb = (size_t)ks2 * KCH2;

    uint32_t aOff[2], bOff[2];
    #pragma unroll
    for (int i = 0; i < 2; i++)
        aOff[i] = (uint32_t)((wm * 32 + i * 16 + trow + ((th & 1) << 3)) * ROWB + ((th >> 1) << 4));
    #pragma unroll
    for (int j = 0; j < 2; j++)
        bOff[j] = (uint32_t)((wn * 32 + j * 16 + trow + ((th >> 1) << 3)) * ROWB + ((th & 1) << 4));

    float acc[2][4][4];
    #pragma unroll
    for (int i = 0; i < 2; i++)
        #pragma unroll
        for (int j = 0; j < 4; j++)
            #pragma unroll
            for (int r = 0; r < 4; r++) acc[i][j][r] = 0.f;

    stage_chunk(sb, tid, g_Ehi, g_Elo, EHH, m0, kb, g_W1thi, g_W1tlo, EHH, n0, kb);
    CP_COMMIT();
    for (int c = 0; c < 25; c++) {
        if (c + 1 < 25) {
            stage_chunk(sb + ((c + 1) & 1) * BUFSZ, tid,
                        g_Ehi, g_Elo, EHH, m0, kb + (size_t)(c + 1) * 64,
                        g_W1thi, g_W1tlo, EHH, n0, kb + (size_t)(c + 1) * 64);
            CP_COMMIT();
            CP_WAIT1();
        } else {
            CP_WAIT0();
        }
        __syncthreads();
        mma_chunk(sb + (c & 1) * BUFSZ, aOff, bOff, acc);
        __syncthreads();
    }

    // epilogue: fp32 partials
    int gid = lid >> 2, tid4 = lid & 3;
    #pragma unroll
    for (int i = 0; i < 2; i++) {
        #pragma unroll
        for (int jj = 0; jj < 4; jj++) {
            int col = n0 + wn * 32 + jj * 8 + tid4 * 2;
            int r0  = m0 + wm * 32 + i * 16 + gid;
            float2 lo = {acc[i][jj][0], acc[i][jj][1]};
            float2 hi = {acc[i][jj][2], acc[i][jj][3]};
            *(float2*)&g_h1p[((size_t)ks2 * BATCH + r0) * N2P + col]     = lo;
            *(float2*)&g_h1p[((size_t)ks2 * BATCH + r0 + 8) * N2P + col] = hi;
        }
    }
}

// ============================================================
// 8) reduce split-K + bias + leaky + tiny MLP + gather
// ============================================================
__global__ void k_tail(const float* __restrict__ b1, const float* __restrict__ w2,
                       const float* __restrict__ b2, const float* __restrict__ w3,
                       const float* __restrict__ b3, const int* __restrict__ actions,
                       float* __restrict__ out) {
    __shared__ float w2s[144], w3s[48], b2s[12], b3s[4], b1s[12];
    int a = blockIdx.y;
    int t = threadIdx.x;
    for (int i = t; i < 144; i += 128) w2s[i] = w2[a * 144 + i];
    if (t < 48)  w3s[t] = w3[a * 48 + t];
    if (t < 12)  { b2s[t] = b2[a * 12 + t]; b1s[t] = b1[a * 12 + t]; }
    if (t < 4)   b3s[t] = b3[a * 4 + t];
    __syncthreads();
    int b = blockIdx.x * 128 + t;
    float x[12];
    {
        const float4* p0 = (const float4*)&g_h1p[(size_t)b * N2P + a * 12];
        const float4* p1 = (const float4*)&g_h1p[((size_t)BATCH + b) * N2P + a * 12];
        float4 q0 = p0[0], q1 = p0[1], q2 = p0[2];
        float4 r0 = p1[0], r1 = p1[1], r2 = p1[2];
        x[0] = q0.x + r0.x; x[1] = q0.y + r0.y; x[2]  = q0.z + r0.z; x[3]  = q0.w + r0.w;
        x[4] = q1.x + r1.x; x[5] = q1.y + r1.y; x[6]  = q1.z + r1.z; x[7]  = q1.w + r1.w;
        x[8] = q2.x + r2.x; x[9] = q2.y + r2.y; x[10] = q2.z + r2.z; x[11] = q2.w + r2.w;
    }
    #pragma unroll
    for (int k = 0; k < 12; k++) x[k] = leaky(x[k] + b1s[k]);
    int act = actions[(size_t)a * BATCH + b];
    float q = b3s[act];
    #pragma unroll
    for (int j = 0; j < 12; j++) {
        float s = b2s[j];
        #pragma unroll
        for (int k = 0; k < 12; k++) s += x[k] * w2s[k * 12 + j];
        q += leaky(s) * w3s[j * 4 + act];
    }
    out[(size_t)a * BATCH + b] = q;
}

// ============================================================
extern "C" void kernel_launch(void* const* d_in, const int* in_sizes, int n_in,
                              void* d_out, int out_size) {
    const float* states = (const float*)d_in[0];
    const float* ehh_w  = (const float*)d_in[1];
    const float* anova  = (const float*)d_in[2];
    const float* w1     = (const float*)d_in[3];
    const float* b1     = (const float*)d_in[4];
    const float* w2     = (const float*)d_in[5];
    const float* b2     = (const float*)d_in[6];
    const float* w3     = (const float*)d_in[7];
    const float* b3     = (const float*)d_in[8];
    const int* actions  = (const int*)d_in[9];
    const int* adj      = (const int*)d_in[10];
    float* out = (float*)d_out;

    cudaFuncSetAttribute(k_mm1, cudaFuncAttributeMaxDynamicSharedMemorySize, SMEM_TOT);
    cudaFuncSetAttribute(k_mm2, cudaFuncAttributeMaxDynamicSharedMemorySize, SMEM_TOT);

    k_stats  <<<K1, 256>>>(states);
    k_winner <<<1, 256>>>(adj);
    k_w1t    <<<N2P, 256>>>(anova, w1, adj);
    k_aprep  <<<BATCH, 256>>>(states);
    k_btrans <<<dim3(EHH / 32, KP1 / 32), dim3(32, 8)>>>(ehh_w);
    k_mm1    <<<dim3(EHH / 64, BATCH / 128), 256, SMEM_TOT>>>();
    k_mm2    <<<dim3(N2P / 64, BATCH / 128, KSPLIT2), 256, SMEM_TOT>>>();
    k_tail   <<<dim3(BATCH / 128, N_AGENT), 128>>>(b1, w2, b2, w3, b3, actions, out);
}

// round 8
// speedup vs baseline: 3.2976x; 1.0988x over previous
#include <cuda_runtime.h>
#include <cuda_bf16.h>
#include <cstdint>

#define N_AGENT 25
#define N_S     32
#define BATCH   2048
#define K1      800
#define KP1     832            // 13*64
#define EHH     3200           // 50*64
#define N2      300
#define N2P     320
#define N_EDGE  300
#define KSPLIT2 3

#define ROWB    144

// ---- mm1 smem layout (128x128 tile): A 128 rows, B 128 rows, hi+lo ----
#define M1_AHI  0
#define M1_ALO  18432
#define M1_BHI  36864
#define M1_BLO  55296
#define M1_BUF  73728
#define M1_TOT  (2 * M1_BUF)
// ---- mm2 smem layout (128x64): A 128 rows, B 64 rows ----
#define M2_AHI  0
#define M2_ALO  18432
#define M2_BHI  36864
#define M2_BLO  46080
#define M2_BUF  55296
#define M2_TOT  (2 * M2_BUF)

// ---- device scratch ----
__device__ float g_mu[K1];
__device__ float g_rstd[K1];
__device__ int   g_wtag[EHH];
__device__ __nv_bfloat16 g_Ahi[(size_t)BATCH * KP1];
__device__ __nv_bfloat16 g_Alo[(size_t)BATCH * KP1];
__device__ __nv_bfloat16 g_Bthi[(size_t)EHH * KP1];
__device__ __nv_bfloat16 g_Btlo[(size_t)EHH * KP1];
__device__ __nv_bfloat16 g_Ehi[(size_t)BATCH * EHH];
__device__ __nv_bfloat16 g_Elo[(size_t)BATCH * EHH];
__device__ __nv_bfloat16 g_W1thi[(size_t)N2P * EHH];
__device__ __nv_bfloat16 g_W1tlo[(size_t)N2P * EHH];
__device__ float g_h1p[(size_t)KSPLIT2 * BATCH * N2P];

__device__ __forceinline__ float leaky(float x) { return x >= 0.f ? x : 0.01f * x; }
__device__ __forceinline__ void bf16split(float x, __nv_bfloat16& h, __nv_bfloat16& l) {
    h = __float2bfloat16(x);
    l = __float2bfloat16(x - __bfloat162float(h));
}
__device__ __forceinline__ uint32_t smem_u32(const void* p) {
    uint32_t a;
    asm("{ .reg .u64 t; cvta.to.shared.u64 t, %1; cvt.u32.u64 %0, t; }" : "=r"(a) : "l"(p));
    return a;
}
__device__ __forceinline__ uint32_t packbf2(float x, float y) {
    __nv_bfloat162 t = __floats2bfloat162_rn(x, y);
    return *(uint32_t*)&t;
}

#define CP16(dst, src) asm volatile("cp.async.cg.shared.global [%0], [%1], 16;" :: "r"(dst), "l"(src))
#define CP_COMMIT()    asm volatile("cp.async.commit_group;")
#define CP_WAIT0()     asm volatile("cp.async.wait_group 0;")
#define CP_WAIT1()     asm volatile("cp.async.wait_group 1;")
#define LDM4(r, addr)  asm volatile("ldmatrix.sync.aligned.m8n8.x4.shared.b16 {%0,%1,%2,%3}, [%4];" \
    : "=r"((r)[0]), "=r"((r)[1]), "=r"((r)[2]), "=r"((r)[3]) : "r"(addr))

__device__ __forceinline__ void mmabf(float* c, const uint32_t* a, uint32_t b0, uint32_t b1) {
    asm volatile(
        "mma.sync.aligned.m16n8k16.row.col.f32.bf16.bf16.f32 "
        "{%0,%1,%2,%3},{%4,%5,%6,%7},{%8,%9},{%0,%1,%2,%3};"
        : "+f"(c[0]), "+f"(c[1]), "+f"(c[2]), "+f"(c[3])
        : "r"(a[0]), "r"(a[1]), "r"(a[2]), "r"(a[3]), "r"(b0), "r"(b1));
}

// ============================================================
// 1) batch-norm stats (coalesced: block = agent, lane = feature)
// ============================================================
__global__ void k_stats(const float* __restrict__ states) {
    int a = blockIdx.x;
    int w = threadIdx.x >> 5, lane = threadIdx.x & 31;
    float sum = 0.f, sq = 0.f;
    const float* base = states + (size_t)a * BATCH * N_S + lane;
    for (int b = w; b < BATCH; b += 8) {
        float v = base[(size_t)b * N_S];
        sum += v; sq += v * v;
    }
    __shared__ float ss[8][32], qq[8][32];
    ss[w][lane] = sum; qq[w][lane] = sq;
    __syncthreads();
    if (w == 0) {
        float S = 0.f, Q = 0.f;
        #pragma unroll
        for (int i = 0; i < 8; i++) { S += ss[i][lane]; Q += qq[i][lane]; }
        float mu  = S * (1.f / BATCH);
        float var = Q * (1.f / BATCH) - mu * mu;
        g_mu[a * 32 + lane]   = mu;
        g_rstd[a * 32 + lane] = rsqrtf(var + 1e-5f);
    }
}

// ============================================================
// 2) winner tags via priority atomicMax (== sequential last-write-wins:
//    pass2 (.at[adj[:,3]]) beats pass1, higher e beats lower within a pass)
//    FIX vs R7: block was 256 threads but N_EDGE=300 -> edges 256..299 dropped.
//    Now 512 threads.
// ============================================================
__global__ void k_winner(const int* __restrict__ adj) {
    int t = threadIdx.x;
    for (int i = t; i < EHH; i += 512) g_wtag[i] = -1;
    __syncthreads();
    if (t < N_EDGE) {
        int r1  = adj[t * 4 + 1];
        int r3  = adj[t * 4 + 3];
        int src = adj[t * 4 + 0];
        atomicMax(&g_wtag[r1], (t << 16) | src);
        atomicMax(&g_wtag[r3], ((t + N_EDGE) << 16) | src);
    }
}

// ============================================================
// 3) W1eff^T bf16 hi/lo: [320 n][3200 k]; coalesced w1 reads
//    grid (26, 25): x = agent (25 => zero-pad block), y = k block of 128
// ============================================================
__global__ void k_w1t(const float* __restrict__ anova, const float* __restrict__ w1) {
    int a  = blockIdx.x;
    int kb = blockIdx.y * 128;
    int t  = threadIdx.x;
    if (a == N_AGENT) {           // zero rows 300..319
        for (int idx = t; idx < 20 * 64; idx += 256) {
            int n = N2 + idx / 64, kp = idx % 64;
            *(uint32_t*)(g_W1thi + (size_t)n * EHH + kb + kp * 2) = 0u;
            *(uint32_t*)(g_W1tlo + (size_t)n * EHH + kb + kp * 2) = 0u;
        }
        return;
    }
    __shared__ float att_s[128];
    __shared__ __nv_bfloat16 oh[12][128], ol[12][128];
    if (t < 128) {
        int k = kb + t;
        int tag = g_wtag[k];
        float neigh = (tag >= 0) ? anova[(size_t)(EHH + (tag & 0xFFFF)) * N_AGENT + a] : 0.f;
        att_s[t] = anova[(size_t)k * N_AGENT + a] + neigh;
    }
    __syncthreads();
    #pragma unroll
    for (int r = 0; r < 6; r++) {
        int idx = t + 256 * r;          // 0..1535
        int k = idx / 12, kk = idx % 12;
        float v = att_s[k] * w1[((size_t)a * EHH + kb + k) * 12 + kk];
        __nv_bfloat16 h, l; bf16split(v, h, l);
        oh[kk][k] = h; ol[kk][k] = l;
    }
    __syncthreads();
    #pragma unroll
    for (int r = 0; r < 3; r++) {
        int idx = t + 256 * r;          // 0..767 (u32 pairs)
        int kk = idx / 64, kp = idx % 64;
        int n = a * 12 + kk;
        *(uint32_t*)(g_W1thi + (size_t)n * EHH + kb + kp * 2) = *(uint32_t*)&oh[kk][kp * 2];
        *(uint32_t*)(g_W1tlo + (size_t)n * EHH + kb + kp * 2) = *(uint32_t*)&ol[kk][kp * 2];
    }
}

// ============================================================
// 4) A prep: normalized states -> bf16 hi/lo [2048][832]
// ============================================================
__global__ void k_aprep(const float* __restrict__ states) {
    int b = blockIdx.x;
    for (int k = threadIdx.x; k < KP1; k += 256) {
        float x = 0.f;
        if (k < K1) {
            int a = k >> 5, s = k & 31;
            x = (states[((size_t)a * BATCH + b) * N_S + s] - g_mu[k]) * g_rstd[k];
        }
        __nv_bfloat16 h, l; bf16split(x, h, l);
        g_Ahi[(size_t)b * KP1 + k] = h;
        g_Alo[(size_t)b * KP1 + k] = l;
    }
}

// ============================================================
// 5) B prep: transpose ehh_w [800][3200] -> Bt hi/lo [3200][832]
// ============================================================
__global__ void k_btrans(const float* __restrict__ ehh_w) {
    __shared__ float tl[32][33];
    int n0 = blockIdx.x * 32;
    int k0 = blockIdx.y * 32;
    int tx = threadIdx.x, ty = threadIdx.y;   // 32 x 8
    #pragma unroll
    for (int i = 0; i < 4; i++) {
        int kr = ty + 8 * i;
        int kg = k0 + kr;
        tl[kr][tx] = (kg < K1) ? ehh_w[(size_t)kg * EHH + n0 + tx] : 0.f;
    }
    __syncthreads();
    #pragma unroll
    for (int i = 0; i < 4; i++) {
        int nr = ty + 8 * i;
        float v = tl[tx][nr];
        __nv_bfloat16 h, l; bf16split(v, h, l);
        g_Bthi[(size_t)(n0 + nr) * KP1 + k0 + tx] = h;
        g_Btlo[(size_t)(n0 + nr) * KP1 + k0 + tx] = l;
    }
}

// ============================================================
// 6) GEMM1 HMMA: emb = leaky(Anorm @ ehh_w), bf16x3
//    block tile 128(m) x 128(n), warp tile 32x64, 13 K-chunks of 64
// ============================================================
__global__ void __launch_bounds__(256) k_mm1() {
    extern __shared__ __align__(16) char smem[];
    uint32_t sb = smem_u32(smem);
    int tid = threadIdx.x;
    int wid = tid >> 5, lid = tid & 31;
    int wm = wid & 3, wn = wid >> 2;
    int trow = lid & 7, th = lid >> 3;
    int m0 = blockIdx.y * 128, n0 = blockIdx.x * 128;

    uint32_t aOff[2], bOff[4];
    #pragma unroll
    for (int i = 0; i < 2; i++)
        aOff[i] = (uint32_t)((wm * 32 + i * 16 + trow + ((th & 1) << 3)) * ROWB + ((th >> 1) << 4));
    #pragma unroll
    for (int j = 0; j < 4; j++)
        bOff[j] = (uint32_t)((wn * 64 + j * 16 + trow + ((th >> 1) << 3)) * ROWB + ((th & 1) << 4));

    float acc[2][8][4];
    #pragma unroll
    for (int i = 0; i < 2; i++)
        #pragma unroll
        for (int j = 0; j < 8; j++)
            #pragma unroll
            for (int r = 0; r < 4; r++) acc[i][j][r] = 0.f;

    #define STAGE1(buf, c) do {                                                         \
        uint32_t base = sb + (buf) * M1_BUF;                                            \
        size_t col = (size_t)(c) * 64;                                                  \
        _Pragma("unroll")                                                               \
        for (int j = 0; j < 4; j++) {                                                   \
            int lin = tid + 256 * j;                                                    \
            int row = lin >> 3, u = lin & 7;                                            \
            uint32_t d = base + row * ROWB + u * 16;                                    \
            CP16(d + M1_AHI, g_Ahi  + (size_t)(m0 + row) * KP1 + col + u * 8);          \
            CP16(d + M1_ALO, g_Alo  + (size_t)(m0 + row) * KP1 + col + u * 8);          \
            CP16(d + M1_BHI, g_Bthi + (size_t)(n0 + row) * KP1 + col + u * 8);          \
            CP16(d + M1_BLO, g_Btlo + (size_t)(n0 + row) * KP1 + col + u * 8);          \
        }                                                                               \
    } while (0)

    STAGE1(0, 0);
    CP_COMMIT();
    for (int c = 0; c < 13; c++) {
        if (c + 1 < 13) { STAGE1((c + 1) & 1, c + 1); CP_COMMIT(); CP_WAIT1(); }
        else CP_WAIT0();
        __syncthreads();
        uint32_t base = sb + (c & 1) * M1_BUF;
        #pragma unroll
        for (int ks = 0; ks < 4; ks++) {
            uint32_t ah[2][4], al[2][4], bh[4][4], bl[4][4];
            #pragma unroll
            for (int i = 0; i < 2; i++) {
                LDM4(ah[i], base + M1_AHI + aOff[i] + ks * 32);
                LDM4(al[i], base + M1_ALO + aOff[i] + ks * 32);
            }
            #pragma unroll
            for (int j = 0; j < 4; j++) {
                LDM4(bh[j], base + M1_BHI + bOff[j] + ks * 32);
                LDM4(bl[j], base + M1_BLO + bOff[j] + ks * 32);
            }
            #pragma unroll
            for (int i = 0; i < 2; i++)
                #pragma unroll
                for (int jj = 0; jj < 8; jj++) {
                    float* cc = acc[i][jj];
                    uint32_t h0 = bh[jj >> 1][(jj & 1) * 2], h1 = bh[jj >> 1][(jj & 1) * 2 + 1];
                    uint32_t l0 = bl[jj >> 1][(jj & 1) * 2], l1 = bl[jj >> 1][(jj & 1) * 2 + 1];
                    mmabf(cc, ah[i], h0, h1);
                    mmabf(cc, al[i], h0, h1);
                    mmabf(cc, ah[i], l0, l1);
                }
        }
        __syncthreads();
    }
    #undef STAGE1

    // epilogue: leaky + bf16 hi/lo split
    int gid = lid >> 2, tid4 = lid & 3;
    #pragma unroll
    for (int i = 0; i < 2; i++) {
        #pragma unroll
        for (int jj = 0; jj < 8; jj++) {
            int col = n0 + wn * 64 + jj * 8 + tid4 * 2;
            int r0  = m0 + wm * 32 + i * 16 + gid;
            float v0 = leaky(acc[i][jj][0]), v1 = leaky(acc[i][jj][1]);
            float v2 = leaky(acc[i][jj][2]), v3 = leaky(acc[i][jj][3]);
            __nv_bfloat16 h0, l0, h1, l1, h2, l2, h3, l3;
            bf16split(v0, h0, l0); bf16split(v1, h1, l1);
            bf16split(v2, h2, l2); bf16split(v3, h3, l3);
            *(uint32_t*)(g_Ehi + (size_t)r0 * EHH + col)       = packbf2(__bfloat162float(h0), __bfloat162float(h1));
            *(uint32_t*)(g_Elo + (size_t)r0 * EHH + col)       = packbf2(__bfloat162float(l0), __bfloat162float(l1));
            *(uint32_t*)(g_Ehi + (size_t)(r0 + 8) * EHH + col) = packbf2(__bfloat162float(h2), __bfloat162float(h3));
            *(uint32_t*)(g_Elo + (size_t)(r0 + 8) * EHH + col) = packbf2(__bfloat162float(l2), __bfloat162float(l3));
        }
    }
}

// ============================================================
// 7) GEMM2 HMMA: h1 partials = emb @ W1eff (bf16x3, split-K=3)
//    block tile 128 x 64; chunks 17/17/16 of K=64
// ============================================================
__global__ void __launch_bounds__(256) k_mm2() {
    extern __shared__ __align__(16) char smem[];
    uint32_t sb = smem_u32(smem);
    int tid = threadIdx.x;
    int wid = tid >> 5, lid = tid & 31;
    int wm = wid >> 1, wn = wid & 1;
    int trow = lid & 7, th = lid >> 3;
    int n0 = blockIdx.x * 64, m0 = blockIdx.y * 128;
    int ks2 = blockIdx.z;
    int cstart = ks2 * 17;
    int nch = (ks2 == 2) ? 16 : 17;

    uint32_t aOff[2], bOff[2];
    #pragma unroll
    for (int i = 0; i < 2; i++)
        aOff[i] = (uint32_t)((wm * 32 + i * 16 + trow + ((th & 1) << 3)) * ROWB + ((th >> 1) << 4));
    #pragma unroll
    for (int j = 0; j < 2; j++)
        bOff[j] = (uint32_t)((wn * 32 + j * 16 + trow + ((th >> 1) << 3)) * ROWB + ((th & 1) << 4));

    float acc[2][4][4];
    #pragma unroll
    for (int i = 0; i < 2; i++)
        #pragma unroll
        for (int j = 0; j < 4; j++)
            #pragma unroll
            for (int r = 0; r < 4; r++) acc[i][j][r] = 0.f;

    #define STAGE2(buf, c) do {                                                         \
        uint32_t base = sb + (buf) * M2_BUF;                                            \
        size_t col = (size_t)(cstart + (c)) * 64;                                       \
        _Pragma("unroll")                                                               \
        for (int j = 0; j < 4; j++) {                                                   \
            int lin = tid + 256 * j;                                                    \
            int row = lin >> 3, u = lin & 7;                                            \
            uint32_t d = base + row * ROWB + u * 16;                                    \
            CP16(d + M2_AHI, g_Ehi + (size_t)(m0 + row) * EHH + col + u * 8);           \
            CP16(d + M2_ALO, g_Elo + (size_t)(m0 + row) * EHH + col + u * 8);           \
        }                                                                               \
        _Pragma("unroll")                                                               \
        for (int j = 0; j < 2; j++) {                                                   \
            int lin = tid + 256 * j;                                                    \
            int row = lin >> 3, u = lin & 7;                                            \
            uint32_t d = base + row * ROWB + u * 16;                                    \
            CP16(d + M2_BHI, g_W1thi + (size_t)(n0 + row) * EHH + col + u * 8);         \
            CP16(d + M2_BLO, g_W1tlo + (size_t)(n0 + row) * EHH + col + u * 8);         \
        }                                                                               \
    } while (0)

    STAGE2(0, 0);
    CP_COMMIT();
    for (int c = 0; c < nch; c++) {
        if (c + 1 < nch) { STAGE2((c + 1) & 1, c + 1); CP_COMMIT(); CP_WAIT1(); }
        else CP_WAIT0();
        __syncthreads();
        uint32_t base = sb + (c & 1) * M2_BUF;
        #pragma unroll
        for (int ks = 0; ks < 4; ks++) {
            uint32_t ah[2][4], al[2][4], bh[2][4], bl[2][4];
            #pragma unroll
            for (int i = 0; i < 2; i++) {
                LDM4(ah[i], base + M2_AHI + aOff[i] + ks * 32);
                LDM4(al[i], base + M2_ALO + aOff[i] + ks * 32);
            }
            #pragma unroll
            for (int j = 0; j < 2; j++) {
                LDM4(bh[j], base + M2_BHI + bOff[j] + ks * 32);
                LDM4(bl[j], base + M2_BLO + bOff[j] + ks * 32);
            }
            #pragma unroll
            for (int i = 0; i < 2; i++)
                #pragma unroll
                for (int jj = 0; jj < 4; jj++) {
                    float* cc = acc[i][jj];
                    uint32_t h0 = bh[jj >> 1][(jj & 1) * 2], h1 = bh[jj >> 1][(jj & 1) * 2 + 1];
                    uint32_t l0 = bl[jj >> 1][(jj & 1) * 2], l1 = bl[jj >> 1][(jj & 1) * 2 + 1];
                    mmabf(cc, ah[i], h0, h1);
                    mmabf(cc, al[i], h0, h1);
                    mmabf(cc, ah[i], l0, l1);
                }
        }
        __syncthreads();
    }
    #undef STAGE2

    int gid = lid >> 2, tid4 = lid & 3;
    #pragma unroll
    for (int i = 0; i < 2; i++) {
        #pragma unroll
        for (int jj = 0; jj < 4; jj++) {
            int col = n0 + wn * 32 + jj * 8 + tid4 * 2;
            int r0  = m0 + wm * 32 + i * 16 + gid;
            float2 lo = {acc[i][jj][0], acc[i][jj][1]};
            float2 hi = {acc[i][jj][2], acc[i][jj][3]};
            *(float2*)&g_h1p[((size_t)ks2 * BATCH + r0) * N2P + col]     = lo;
            *(float2*)&g_h1p[((size_t)ks2 * BATCH + r0 + 8) * N2P + col] = hi;
        }
    }
}

// ============================================================
// 8) reduce split-K + bias + leaky + tiny MLP + gather
// ============================================================
__global__ void k_tail(const float* __restrict__ b1, const float* __restrict__ w2,
                       const float* __restrict__ b2, const float* __restrict__ w3,
                       const float* __restrict__ b3, const int* __restrict__ actions,
                       float* __restrict__ out) {
    __shared__ float w2s[144], w3s[48], b2s[12], b3s[4], b1s[12];
    int a = blockIdx.y;
    int t = threadIdx.x;
    for (int i = t; i < 144; i += 128) w2s[i] = w2[a * 144 + i];
    if (t < 48)  w3s[t] = w3[a * 48 + t];
    if (t < 12)  { b2s[t] = b2[a * 12 + t]; b1s[t] = b1[a * 12 + t]; }
    if (t < 4)   b3s[t] = b3[a * 4 + t];
    __syncthreads();
    int b = blockIdx.x * 128 + t;
    float x[12] = {0,0,0,0,0,0,0,0,0,0,0,0};
    #pragma unroll
    for (int ks = 0; ks < KSPLIT2; ks++) {
        const float4* p = (const float4*)&g_h1p[((size_t)ks * BATCH + b) * N2P + a * 12];
        float4 q0 = p[0], q1 = p[1], q2 = p[2];
        x[0] += q0.x; x[1] += q0.y; x[2]  += q0.z; x[3]  += q0.w;
        x[4] += q1.x; x[5] += q1.y; x[6]  += q1.z; x[7]  += q1.w;
        x[8] += q2.x; x[9] += q2.y; x[10] += q2.z; x[11] += q2.w;
    }
    #pragma unroll
    for (int k = 0; k < 12; k++) x[k] = leaky(x[k] + b1s[k]);
    int act = actions[(size_t)a * BATCH + b];
    float q = b3s[act];
    #pragma unroll
    for (int j = 0; j < 12; j++) {
        float s = b2s[j];
        #pragma unroll
        for (int k = 0; k < 12; k++) s += x[k] * w2s[k * 12 + j];
        q += leaky(s) * w3s[j * 4 + act];
    }
    out[(size_t)a * BATCH + b] = q;
}

// ============================================================
extern "C" void kernel_launch(void* const* d_in, const int* in_sizes, int n_in,
                              void* d_out, int out_size) {
    const float* states = (const float*)d_in[0];
    const float* ehh_w  = (const float*)d_in[1];
    const float* anova  = (const float*)d_in[2];
    const float* w1     = (const float*)d_in[3];
    const float* b1     = (const float*)d_in[4];
    const float* w2     = (const float*)d_in[5];
    const float* b2     = (const float*)d_in[6];
    const float* w3     = (const float*)d_in[7];
    const float* b3     = (const float*)d_in[8];
    const int* actions  = (const int*)d_in[9];
    const int* adj      = (const int*)d_in[10];
    float* out = (float*)d_out;

    cudaFuncSetAttribute(k_mm1, cudaFuncAttributeMaxDynamicSharedMemorySize, M1_TOT);
    cudaFuncSetAttribute(k_mm2, cudaFuncAttributeMaxDynamicSharedMemorySize, M2_TOT);

    k_stats  <<<N_AGENT, 256>>>(states);
    k_winner <<<1, 512>>>(adj);
    k_w1t    <<<dim3(N_AGENT + 1, EHH / 128), 256>>>(anova, w1);
    k_aprep  <<<BATCH, 256>>>(states);
    k_btrans <<<dim3(EHH / 32, KP1 / 32), dim3(32, 8)>>>(ehh_w);
    k_mm1    <<<dim3(EHH / 128, BATCH / 128), 256, M1_TOT>>>();
    k_mm2    <<<dim3(N2P / 64, BATCH / 128, KSPLIT2), 256, M2_TOT>>>();
    k_tail   <<<dim3(BATCH / 128, N_AGENT), 128>>>(b1, w2, b2, w3, b3, actions, out);
}

// round 9
// speedup vs baseline: 3.2987x; 1.0003x over previous
#include <cuda_runtime.h>
#include <cuda_bf16.h>
#include <cstdint>

#define N_AGENT 25
#define N_S     32
#define BATCH   2048
#define K1      800
#define KP1     832            // 13*64
#define EHH     3200           // 50*64
#define N2      300
#define N2P     320
#define N_EDGE  300
#define KSPLIT2 3

#define ROWB    144

// ---- mm1 smem layout (128x128 tile): A 128 rows, B 128 rows, hi+lo ----
#define M1_AHI  0
#define M1_ALO  18432
#define M1_BHI  36864
#define M1_BLO  55296
#define M1_BUF  73728
#define M1_TOT  (2 * M1_BUF)
// ---- mm2 smem layout (128x64): A 128 rows, B 64 rows ----
#define M2_AHI  0
#define M2_ALO  18432
#define M2_BHI  36864
#define M2_BLO  46080
#define M2_BUF  55296
#define M2_TOT  (2 * M2_BUF)

// ---- device scratch ----
__device__ float g_mu[K1];
__device__ float g_rstd[K1];
__device__ int   g_wtag[EHH];
__device__ __nv_bfloat16 g_Ahi[(size_t)BATCH * KP1];
__device__ __nv_bfloat16 g_Alo[(size_t)BATCH * KP1];
__device__ __nv_bfloat16 g_Bthi[(size_t)EHH * KP1];
__device__ __nv_bfloat16 g_Btlo[(size_t)EHH * KP1];
__device__ __nv_bfloat16 g_Ehi[(size_t)BATCH * EHH];
__device__ __nv_bfloat16 g_Elo[(size_t)BATCH * EHH];
__device__ __nv_bfloat16 g_W1thi[(size_t)N2P * EHH];
__device__ __nv_bfloat16 g_W1tlo[(size_t)N2P * EHH];
__device__ float g_h1p[(size_t)KSPLIT2 * BATCH * N2P];

__device__ __forceinline__ float leaky(float x) { return x >= 0.f ? x : 0.01f * x; }
__device__ __forceinline__ void bf16split(float x, __nv_bfloat16& h, __nv_bfloat16& l) {
    h = __float2bfloat16(x);
    l = __float2bfloat16(x - __bfloat162float(h));
}
__device__ __forceinline__ uint32_t smem_u32(const void* p) {
    uint32_t a;
    asm("{ .reg .u64 t; cvta.to.shared.u64 t, %1; cvt.u32.u64 %0, t; }" : "=r"(a) : "l"(p));
    return a;
}
__device__ __forceinline__ uint32_t packbf2(float x, float y) {
    __nv_bfloat162 t = __floats2bfloat162_rn(x, y);
    return *(uint32_t*)&t;
}

#define CP16(dst, src) asm volatile("cp.async.cg.shared.global [%0], [%1], 16;" :: "r"(dst), "l"(src))
#define CP_COMMIT()    asm volatile("cp.async.commit_group;")
#define CP_WAIT0()     asm volatile("cp.async.wait_group 0;")
#define CP_WAIT1()     asm volatile("cp.async.wait_group 1;")
#define LDM4(r, addr)  asm volatile("ldmatrix.sync.aligned.m8n8.x4.shared.b16 {%0,%1,%2,%3}, [%4];" \
    : "=r"((r)[0]), "=r"((r)[1]), "=r"((r)[2]), "=r"((r)[3]) : "r"(addr))

__device__ __forceinline__ void mmabf(float* c, const uint32_t* a, uint32_t b0, uint32_t b1) {
    asm volatile(
        "mma.sync.aligned.m16n8k16.row.col.f32.bf16.bf16.f32 "
        "{%0,%1,%2,%3},{%4,%5,%6,%7},{%8,%9},{%0,%1,%2,%3};"
        : "+f"(c[0]), "+f"(c[1]), "+f"(c[2]), "+f"(c[3])
        : "r"(a[0]), "r"(a[1]), "r"(a[2]), "r"(a[3]), "r"(b0), "r"(b1));
}

// ============================================================
// 1) batch-norm stats (coalesced: block = agent, lane = feature)
// ============================================================
__global__ void k_stats(const float* __restrict__ states) {
    int a = blockIdx.x;
    int w = threadIdx.x >> 5, lane = threadIdx.x & 31;
    float sum = 0.f, sq = 0.f;
    const float* base = states + (size_t)a * BATCH * N_S + lane;
    for (int b = w; b < BATCH; b += 8) {
        float v = base[(size_t)b * N_S];
        sum += v; sq += v * v;
    }
    __shared__ float ss[8][32], qq[8][32];
    ss[w][lane] = sum; qq[w][lane] = sq;
    __syncthreads();
    if (w == 0) {
        float S = 0.f, Q = 0.f;
        #pragma unroll
        for (int i = 0; i < 8; i++) { S += ss[i][lane]; Q += qq[i][lane]; }
        float mu  = S * (1.f / BATCH);
        float var = Q * (1.f / BATCH) - mu * mu;
        g_mu[a * 32 + lane]   = mu;
        g_rstd[a * 32 + lane] = rsqrtf(var + 1e-5f);
    }
}

// ============================================================
// 2) winner tags via priority atomicMax (== sequential last-write-wins:
//    pass2 (.at[adj[:,3]]) beats pass1, higher e beats lower within a pass)
//    FIX vs R7: block was 256 threads but N_EDGE=300 -> edges 256..299 dropped.
//    Now 512 threads.
// ============================================================
__global__ void k_winner(const int* __restrict__ adj) {
    int t = threadIdx.x;
    for (int i = t; i < EHH; i += 512) g_wtag[i] = -1;
    __syncthreads();
    if (t < N_EDGE) {
        int r1  = adj[t * 4 + 1];
        int r3  = adj[t * 4 + 3];
        int src = adj[t * 4 + 0];
        atomicMax(&g_wtag[r1], (t << 16) | src);
        atomicMax(&g_wtag[r3], ((t + N_EDGE) << 16) | src);
    }
}

// ============================================================
// 3) W1eff^T bf16 hi/lo: [320 n][3200 k]; coalesced w1 reads
//    grid (26, 25): x = agent (25 => zero-pad block), y = k block of 128
// ============================================================
__global__ void k_w1t(const float* __restrict__ anova, const float* __restrict__ w1) {
    int a  = blockIdx.x;
    int kb = blockIdx.y * 128;
    int t  = threadIdx.x;
    if (a == N_AGENT) {           // zero rows 300..319
        for (int idx = t; idx < 20 * 64; idx += 256) {
            int n = N2 + idx / 64, kp = idx % 64;
            *(uint32_t*)(g_W1thi + (size_t)n * EHH + kb + kp * 2) = 0u;
            *(uint32_t*)(g_W1tlo + (size_t)n * EHH + kb + kp * 2) = 0u;
        }
        return;
    }
    __shared__ float att_s[128];
    __shared__ __nv_bfloat16 oh[12][128], ol[12][128];
    if (t < 128) {
        int k = kb + t;
        int tag = g_wtag[k];
        float neigh = (tag >= 0) ? anova[(size_t)(EHH + (tag & 0xFFFF)) * N_AGENT + a] : 0.f;
        att_s[t] = anova[(size_t)k * N_AGENT + a] + neigh;
    }
    __syncthreads();
    #pragma unroll
    for (int r = 0; r < 6; r++) {
        int idx = t + 256 * r;          // 0..1535
        int k = idx / 12, kk = idx % 12;
        float v = att_s[k] * w1[((size_t)a * EHH + kb + k) * 12 + kk];
        __nv_bfloat16 h, l; bf16split(v, h, l);
        oh[kk][k] = h; ol[kk][k] = l;
    }
    __syncthreads();
    #pragma unroll
    for (int r = 0; r < 3; r++) {
        int idx = t + 256 * r;          // 0..767 (u32 pairs)
        int kk = idx / 64, kp = idx % 64;
        int n = a * 12 + kk;
        *(uint32_t*)(g_W1thi + (size_t)n * EHH + kb + kp * 2) = *(uint32_t*)&oh[kk][kp * 2];
        *(uint32_t*)(g_W1tlo + (size_t)n * EHH + kb + kp * 2) = *(uint32_t*)&ol[kk][kp * 2];
    }
}

// ============================================================
// 4) A prep: normalized states -> bf16 hi/lo [2048][832]
// ============================================================
__global__ void k_aprep(const float* __restrict__ states) {
    int b = blockIdx.x;
    for (int k = threadIdx.x; k < KP1; k += 256) {
        float x = 0.f;
        if (k < K1) {
            int a = k >> 5, s = k & 31;
            x = (states[((size_t)a * BATCH + b) * N_S + s] - g_mu[k]) * g_rstd[k];
        }
        __nv_bfloat16 h, l; bf16split(x, h, l);
        g_Ahi[(size_t)b * KP1 + k] = h;
        g_Alo[(size_t)b * KP1 + k] = l;
    }
}

// ============================================================
// 5) B prep: transpose ehh_w [800][3200] -> Bt hi/lo [3200][832]
// ============================================================
__global__ void k_btrans(const float* __restrict__ ehh_w) {
    __shared__ float tl[32][33];
    int n0 = blockIdx.x * 32;
    int k0 = blockIdx.y * 32;
    int tx = threadIdx.x, ty = threadIdx.y;   // 32 x 8
    #pragma unroll
    for (int i = 0; i < 4; i++) {
        int kr = ty + 8 * i;
        int kg = k0 + kr;
        tl[kr][tx] = (kg < K1) ? ehh_w[(size_t)kg * EHH + n0 + tx] : 0.f;
    }
    __syncthreads();
    #pragma unroll
    for (int i = 0; i < 4; i++) {
        int nr = ty + 8 * i;
        float v = tl[tx][nr];
        __nv_bfloat16 h, l; bf16split(v, h, l);
        g_Bthi[(size_t)(n0 + nr) * KP1 + k0 + tx] = h;
        g_Btlo[(size_t)(n0 + nr) * KP1 + k0 + tx] = l;
    }
}

// ============================================================
// 6) GEMM1 HMMA: emb = leaky(Anorm @ ehh_w), bf16x3
//    block tile 128(m) x 128(n), warp tile 32x64, 13 K-chunks of 64
// ============================================================
__global__ void __launch_bounds__(256) k_mm1() {
    extern __shared__ __align__(16) char smem[];
    uint32_t sb = smem_u32(smem);
    int tid = threadIdx.x;
    int wid = tid >> 5, lid = tid & 31;
    int wm = wid & 3, wn = wid >> 2;
    int trow = lid & 7, th = lid >> 3;
    int m0 = blockIdx.y * 128, n0 = blockIdx.x * 128;

    uint32_t aOff[2], bOff[4];
    #pragma unroll
    for (int i = 0; i < 2; i++)
        aOff[i] = (uint32_t)((wm * 32 + i * 16 + trow + ((th & 1) << 3)) * ROWB + ((th >> 1) << 4));
    #pragma unroll
    for (int j = 0; j < 4; j++)
        bOff[j] = (uint32_t)((wn * 64 + j * 16 + trow + ((th >> 1) << 3)) * ROWB + ((th & 1) << 4));

    float acc[2][8][4];
    #pragma unroll
    for (int i = 0; i < 2; i++)
        #pragma unroll
        for (int j = 0; j < 8; j++)
            #pragma unroll
            for (int r = 0; r < 4; r++) acc[i][j][r] = 0.f;

    #define STAGE1(buf, c) do {                                                         \
        uint32_t base = sb + (buf) * M1_BUF;                                            \
        size_t col = (size_t)(c) * 64;                                                  \
        _Pragma("unroll")                                                               \
        for (int j = 0; j < 4; j++) {                                                   \
            int lin = tid + 256 * j;                                                    \
            int row = lin >> 3, u = lin & 7;                                            \
            uint32_t d = base + row * ROWB + u * 16;                                    \
            CP16(d + M1_AHI, g_Ahi  + (size_t)(m0 + row) * KP1 + col + u * 8);          \
            CP16(d + M1_ALO, g_Alo  + (size_t)(m0 + row) * KP1 + col + u * 8);          \
            CP16(d + M1_BHI, g_Bthi + (size_t)(n0 + row) * KP1 + col + u * 8);          \
            CP16(d + M1_BLO, g_Btlo + (size_t)(n0 + row) * KP1 + col + u * 8);          \
        }                                                                               \
    } while (0)

    STAGE1(0, 0);
    CP_COMMIT();
    for (int c = 0; c < 13; c++) {
        if (c + 1 < 13) { STAGE1((c + 1) & 1, c + 1); CP_COMMIT(); CP_WAIT1(); }
        else CP_WAIT0();
        __syncthreads();
        uint32_t base = sb + (c & 1) * M1_BUF;
        #pragma unroll
        for (int ks = 0; ks < 4; ks++) {
            uint32_t ah[2][4], al[2][4], bh[4][4], bl[4][4];
            #pragma unroll
            for (int i = 0; i < 2; i++) {
                LDM4(ah[i], base + M1_AHI + aOff[i] + ks * 32);
                LDM4(al[i], base + M1_ALO + aOff[i] + ks * 32);
            }
            #pragma unroll
            for (int j = 0; j < 4; j++) {
                LDM4(bh[j], base + M1_BHI + bOff[j] + ks * 32);
                LDM4(bl[j], base + M1_BLO + bOff[j] + ks * 32);
            }
            #pragma unroll
            for (int i = 0; i < 2; i++)
                #pragma unroll
                for (int jj = 0; jj < 8; jj++) {
                    float* cc = acc[i][jj];
                    uint32_t h0 = bh[jj >> 1][(jj & 1) * 2], h1 = bh[jj >> 1][(jj & 1) * 2 + 1];
                    uint32_t l0 = bl[jj >> 1][(jj & 1) * 2], l1 = bl[jj >> 1][(jj & 1) * 2 + 1];
                    mmabf(cc, ah[i], h0, h1);
                    mmabf(cc, al[i], h0, h1);
                    mmabf(cc, ah[i], l0, l1);
                }
        }
        __syncthreads();
    }
    #undef STAGE1

    // epilogue: leaky + bf16 hi/lo split
    int gid = lid >> 2, tid4 = lid & 3;
    #pragma unroll
    for (int i = 0; i < 2; i++) {
        #pragma unroll
        for (int jj = 0; jj < 8; jj++) {
            int col = n0 + wn * 64 + jj * 8 + tid4 * 2;
            int r0  = m0 + wm * 32 + i * 16 + gid;
            float v0 = leaky(acc[i][jj][0]), v1 = leaky(acc[i][jj][1]);
            float v2 = leaky(acc[i][jj][2]), v3 = leaky(acc[i][jj][3]);
            __nv_bfloat16 h0, l0, h1, l1, h2, l2, h3, l3;
            bf16split(v0, h0, l0); bf16split(v1, h1, l1);
            bf16split(v2, h2, l2); bf16split(v3, h3, l3);
            *(uint32_t*)(g_Ehi + (size_t)r0 * EHH + col)       = packbf2(__bfloat162float(h0), __bfloat162float(h1));
            *(uint32_t*)(g_Elo + (size_t)r0 * EHH + col)       = packbf2(__bfloat162float(l0), __bfloat162float(l1));
            *(uint32_t*)(g_Ehi + (size_t)(r0 + 8) * EHH + col) = packbf2(__bfloat162float(h2), __bfloat162float(h3));
            *(uint32_t*)(g_Elo + (size_t)(r0 + 8) * EHH + col) = packbf2(__bfloat162float(l2), __bfloat162float(l3));
        }
    }
}

// ============================================================
// 7) GEMM2 HMMA: h1 partials = emb @ W1eff (bf16x3, split-K=3)
//    block tile 128 x 64; chunks 17/17/16 of K=64
// ============================================================
__global__ void __launch_bounds__(256) k_mm2() {
    extern __shared__ __align__(16) char smem[];
    uint32_t sb = smem_u32(smem);
    int tid = threadIdx.x;
    int wid = tid >> 5, lid = tid & 31;
    int wm = wid >> 1, wn = wid & 1;
    int trow = lid & 7, th = lid >> 3;
    int n0 = blockIdx.x * 64, m0 = blockIdx.y * 128;
    int ks2 = blockIdx.z;
    int cstart = ks2 * 17;
    int nch = (ks2 == 2) ? 16 : 17;

    uint32_t aOff[2], bOff[2];
    #pragma unroll
    for (int i = 0; i < 2; i++)
        aOff[i] = (uint32_t)((wm * 32 + i * 16 + trow + ((th & 1) << 3)) * ROWB + ((th >> 1) << 4));
    #pragma unroll
    for (int j = 0; j < 2; j++)
        bOff[j] = (uint32_t)((wn * 32 + j * 16 + trow + ((th >> 1) << 3)) * ROWB + ((th & 1) << 4));

    float acc[2][4][4];
    #pragma unroll
    for (int i = 0; i < 2; i++)
        #pragma unroll
        for (int j = 0; j < 4; j++)
            #pragma unroll
            for (int r = 0; r < 4; r++) acc[i][j][r] = 0.f;

    #define STAGE2(buf, c) do {                                                         \
        uint32_t base = sb + (buf) * M2_BUF;                                            \
        size_t col = (size_t)(cstart + (c)) * 64;                                       \
        _Pragma("unroll")                                                               \
        for (int j = 0; j < 4; j++) {                                                   \
            int lin = tid + 256 * j;                                                    \
            int row = lin >> 3, u = lin & 7;                                            \
            uint32_t d = base + row * ROWB + u * 16;                                    \
            CP16(d + M2_AHI, g_Ehi + (size_t)(m0 + row) * EHH + col + u * 8);           \
            CP16(d + M2_ALO, g_Elo + (size_t)(m0 + row) * EHH + col + u * 8);           \
        }                                                                               \
        _Pragma("unroll")                                                               \
        for (int j = 0; j < 2; j++) {                                                   \
            int lin = tid + 256 * j;                                                    \
            int row = lin >> 3, u = lin & 7;                                            \
            uint32_t d = base + row * ROWB + u * 16;                                    \
            CP16(d + M2_BHI, g_W1thi + (size_t)(n0 + row) * EHH + col + u * 8);         \
            CP16(d + M2_BLO, g_W1tlo + (size_t)(n0 + row) * EHH + col + u * 8);         \
        }                                                                               \
    } while (0)

    STAGE2(0, 0);
    CP_COMMIT();
    for (int c = 0; c < nch; c++) {
        if (c + 1 < nch) { STAGE2((c + 1) & 1, c + 1); CP_COMMIT(); CP_WAIT1(); }
        else CP_WAIT0();
        __syncthreads();
        uint32_t base = sb + (c & 1) * M2_BUF;
        #pragma unroll
        for (int ks = 0; ks < 4; ks++) {
            uint32_t ah[2][4], al[2][4], bh[2][4], bl[2][4];
            #pragma unroll
            for (int i = 0; i < 2; i++) {
                LDM4(ah[i], base + M2_AHI + aOff[i] + ks * 32);
                LDM4(al[i], base + M2_ALO + aOff[i] + ks * 32);
            }
            #pragma unroll
            for (int j = 0; j < 2; j++) {
                LDM4(bh[j], base + M2_BHI + bOff[j] + ks * 32);
                LDM4(bl[j], base + M2_BLO + bOff[j] + ks * 32);
            }
            #pragma unroll
            for (int i = 0; i < 2; i++)
                #pragma unroll
                for (int jj = 0; jj < 4; jj++) {
                    float* cc = acc[i][jj];
                    uint32_t h0 = bh[jj >> 1][(jj & 1) * 2], h1 = bh[jj >> 1][(jj & 1) * 2 + 1];
                    uint32_t l0 = bl[jj >> 1][(jj & 1) * 2], l1 = bl[jj >> 1][(jj & 1) * 2 + 1];
                    mmabf(cc, ah[i], h0, h1);
                    mmabf(cc, al[i], h0, h1);
                    mmabf(cc, ah[i], l0, l1);
                }
        }
        __syncthreads();
    }
    #undef STAGE2

    int gid = lid >> 2, tid4 = lid & 3;
    #pragma unroll
    for (int i = 0; i < 2; i++) {
        #pragma unroll
        for (int jj = 0; jj < 4; jj++) {
            int col = n0 + wn * 32 + jj * 8 + tid4 * 2;
            int r0  = m0 + wm * 32 + i * 16 + gid;
            float2 lo = {acc[i][jj][0], acc[i][jj][1]};
            float2 hi = {acc[i][jj][2], acc[i][jj][3]};
            *(float2*)&g_h1p[((size_t)ks2 * BATCH + r0) * N2P + col]     = lo;
            *(float2*)&g_h1p[((size_t)ks2 * BATCH + r0 + 8) * N2P + col] = hi;
        }
    }
}

// ============================================================
// 8) reduce split-K + bias + leaky + tiny MLP + gather
// ============================================================
__global__ void k_tail(const float* __restrict__ b1, const float* __restrict__ w2,
                       const float* __restrict__ b2, const float* __restrict__ w3,
                       const float* __restrict__ b3, const int* __restrict__ actions,
                       float* __restrict__ out) {
    __shared__ float w2s[144], w3s[48], b2s[12], b3s[4], b1s[12];
    int a = blockIdx.y;
    int t = threadIdx.x;
    for (int i = t; i < 144; i += 128) w2s[i] = w2[a * 144 + i];
    if (t < 48)  w3s[t] = w3[a * 48 + t];
    if (t < 12)  { b2s[t] = b2[a * 12 + t]; b1s[t] = b1[a * 12 + t]; }
    if (t < 4)   b3s[t] = b3[a * 4 + t];
    __syncthreads();
    int b = blockIdx.x * 128 + t;
    float x[12] = {0,0,0,0,0,0,0,0,0,0,0,0};
    #pragma unroll
    for (int ks = 0; ks < KSPLIT2; ks++) {
        const float4* p = (const float4*)&g_h1p[((size_t)ks * BATCH + b) * N2P + a * 12];
        float4 q0 = p[0], q1 = p[1], q2 = p[2];
        x[0] += q0.x; x[1] += q0.y; x[2]  += q0.z; x[3]  += q0.w;
        x[4] += q1.x; x[5] += q1.y; x[6]  += q1.z; x[7]  += q1.w;
        x[8] += q2.x; x[9] += q2.y; x[10] += q2.z; x[11] += q2.w;
    }
    #pragma unroll
    for (int k = 0; k < 12; k++) x[k] = leaky(x[k] + b1s[k]);
    int act = actions[(size_t)a * BATCH + b];
    float q = b3s[act];
    #pragma unroll
    for (int j = 0; j < 12; j++) {
        float s = b2s[j];
        #pragma unroll
        for (int k = 0; k < 12; k++) s += x[k] * w2s[k * 12 + j];
        q += leaky(s) * w3s[j * 4 + act];
    }
    out[(size_t)a * BATCH + b] = q;
}

// ============================================================
extern "C" void kernel_launch(void* const* d_in, const int* in_sizes, int n_in,
                              void* d_out, int out_size) {
    const float* states = (const float*)d_in[0];
    const float* ehh_w  = (const float*)d_in[1];
    const float* anova  = (const float*)d_in[2];
    const float* w1     = (const float*)d_in[3];
    const float* b1     = (const float*)d_in[4];
    const float* w2     = (const float*)d_in[5];
    const float* b2     = (const float*)d_in[6];
    const float* w3     = (const float*)d_in[7];
    const float* b3     = (const float*)d_in[8];
    const int* actions  = (const int*)d_in[9];
    const int* adj      = (const int*)d_in[10];
    float* out = (float*)d_out;

    cudaFuncSetAttribute(k_mm1, cudaFuncAttributeMaxDynamicSharedMemorySize, M1_TOT);
    cudaFuncSetAttribute(k_mm2, cudaFuncAttributeMaxDynamicSharedMemorySize, M2_TOT);

    k_stats  <<<N_AGENT, 256>>>(states);
    k_winner <<<1, 512>>>(adj);
    k_w1t    <<<dim3(N_AGENT + 1, EHH / 128), 256>>>(anova, w1);
    k_aprep  <<<BATCH, 256>>>(states);
    k_btrans <<<dim3(EHH / 32, KP1 / 32), dim3(32, 8)>>>(ehh_w);
    k_mm1    <<<dim3(EHH / 128, BATCH / 128), 256, M1_TOT>>>();
    k_mm2    <<<dim3(N2P / 64, BATCH / 128, KSPLIT2), 256, M2_TOT>>>();
    k_tail   <<<dim3(BATCH / 128, N_AGENT), 128>>>(b1, w2, b2, w3, b3, actions, out);
}